// round 11
// baseline (speedup 1.0000x reference)
#include <cuda_runtime.h>
#include <cuda_bf16.h>
#include <cuda_fp16.h>

// ---------------- problem dims ----------------
#define NWIN   4096
#define NGT    49
#define NTOK   50
#define CDIM   128
#define HEADS  4
#define HD     32
#define BIMG   64
#define NTPAT  3136
#define WQ_SCALE 0.17677669529663687f   // 32^-0.5

// ---------------- device scratch ----------------
__device__ __half g_Qh [200704u * 128u];
__device__ __half g_Kwh[204800u * 128u];
__device__ __half g_Vwh[204800u * 128u];
__device__ __half g_Vwl[204800u * 128u];
__device__ float  g_bias[HEADS * NGT * NTOK];

// ---------------- helpers ----------------
__device__ __forceinline__ void mma_bf16(float* c, const unsigned* a,
                                         unsigned b0, unsigned b1)
{
    asm volatile("mma.sync.aligned.m16n8k16.row.col.f32.bf16.bf16.f32 "
                 "{%0,%1,%2,%3}, {%4,%5,%6,%7}, {%8,%9}, {%0,%1,%2,%3};"
                 : "+f"(c[0]), "+f"(c[1]), "+f"(c[2]), "+f"(c[3])
                 : "r"(a[0]), "r"(a[1]), "r"(a[2]), "r"(a[3]), "r"(b0), "r"(b1));
}
__device__ __forceinline__ void mma_f16(float* c, const unsigned* a,
                                        unsigned b0, unsigned b1)
{
    asm volatile("mma.sync.aligned.m16n8k16.row.col.f32.f16.f16.f32 "
                 "{%0,%1,%2,%3}, {%4,%5,%6,%7}, {%8,%9}, {%0,%1,%2,%3};"
                 : "+f"(c[0]), "+f"(c[1]), "+f"(c[2]), "+f"(c[3])
                 : "r"(a[0]), "r"(a[1]), "r"(a[2]), "r"(a[3]), "r"(b0), "r"(b1));
}
__device__ __forceinline__ void ldsm_x4(unsigned* r, unsigned addr) {
    asm volatile("ldmatrix.sync.aligned.m8n8.x4.shared.b16 {%0,%1,%2,%3}, [%4];"
                 : "=r"(r[0]), "=r"(r[1]), "=r"(r[2]), "=r"(r[3]) : "r"(addr));
}
__device__ __forceinline__ void ldsm_x4_t(unsigned* r, unsigned addr) {
    asm volatile("ldmatrix.sync.aligned.m8n8.x4.trans.shared.b16 {%0,%1,%2,%3}, [%4];"
                 : "=r"(r[0]), "=r"(r[1]), "=r"(r[2]), "=r"(r[3]) : "r"(addr));
}
__device__ __forceinline__ unsigned s2u(const void* p) {
    return (unsigned)__cvta_generic_to_shared(p);
}
__device__ __forceinline__ unsigned pk2(__nv_bfloat16 a, __nv_bfloat16 b) {
    __nv_bfloat162 t(a, b);
    return *reinterpret_cast<unsigned*>(&t);
}
__device__ __forceinline__ unsigned h2pk(float a, float b) {
    __half2 t = __floats2half2_rn(a, b);
    return *reinterpret_cast<unsigned*>(&t);
}

// =====================================================================
// Split-BF16 projection GEMM (window path only now).
// DST=0 -> g_Qh; DST=1 -> g_Kwh / g_Vwh+g_Vwl
// =====================================================================
#define SBB_STR 136
#define SAB_STR 40
#define SBB_PL  (128 * SBB_STR)
#define SAB_PL  (128 * SAB_STR)
#define GEMM_SMEM ((2 * SBB_PL + 4 * SAB_PL) * 2)   // 110592 bytes

template<int GATHER, int DST>
__global__ void __launch_bounds__(256, 2)
bf16_gemm(const float* __restrict__ A, const float* __restrict__ Aavg,
          const float* __restrict__ W, const float* __restrict__ bias,
          int N, float alpha)
{
    extern __shared__ __nv_bfloat16 sm[];
    __nv_bfloat16* sBh = sm;
    __nv_bfloat16* sBl = sm + SBB_PL;
    __nv_bfloat16* sA  = sm + 2 * SBB_PL;

    const int tid  = threadIdx.x;
    const int lane = tid & 31;
    const int warp = tid >> 5;
    const int wm   = warp >> 2;
    const int wn   = warp & 3;
    const int g4   = lane >> 2;
    const int t4   = lane & 3;
    const int nblk = blockIdx.x * 128;
    const int by   = blockIdx.y;

    const int lr    = lane & 7;
    const int lt8   = ((lane >> 3) & 1) * 8;
    const int lk8   = (lane >> 4) * 8;
    const int bnoff = ((lane >> 4) & 1) * 8;
    const int bk8   = ((lane >> 3) & 1) * 8;

    const int a_row  = tid >> 1;
    const int a_half = (tid & 1) * 16;
    const int m = by * 128 + a_row;
    const float* arow;
    if (GATHER) {
        int w  = m / NTOK;
        int rr = m - w * NTOK;
        arow = (rr < NGT) ? (A    + (size_t)(w * NGT + rr) * CDIM)
                          : (Aavg + (size_t)(w >> 6)       * CDIM);
    } else {
        arow = A + (size_t)m * CDIM;
    }

    // ---- B panel ----
    {
        const int nloc  = (warp & 3) * 32 + lane;
        const int kbase = (warp >> 2) * 64;
        const float* wp = W + nblk + nloc;
        #pragma unroll
        for (int kg = 0; kg < 16; kg++) {
            const int k = kbase + kg * 4;
            float v0 = wp[(size_t)(k + 0) * N];
            float v1 = wp[(size_t)(k + 1) * N];
            float v2 = wp[(size_t)(k + 2) * N];
            float v3 = wp[(size_t)(k + 3) * N];
            __nv_bfloat16 h0 = __float2bfloat16(v0);
            __nv_bfloat16 h1 = __float2bfloat16(v1);
            __nv_bfloat16 h2 = __float2bfloat16(v2);
            __nv_bfloat16 h3 = __float2bfloat16(v3);
            __nv_bfloat16 l0 = __float2bfloat16(v0 - __bfloat162float(h0));
            __nv_bfloat16 l1 = __float2bfloat16(v1 - __bfloat162float(h1));
            __nv_bfloat16 l2 = __float2bfloat16(v2 - __bfloat162float(h2));
            __nv_bfloat16 l3 = __float2bfloat16(v3 - __bfloat162float(h3));
            *(uint2*)(sBh + nloc * SBB_STR + k) = make_uint2(pk2(h0, h1), pk2(h2, h3));
            *(uint2*)(sBl + nloc * SBB_STR + k) = make_uint2(pk2(l0, l1), pk2(l2, l3));
        }
    }

    // ---- A prologue ----
    float4 areg[4];
    #pragma unroll
    for (int j = 0; j < 4; j++)
        areg[j] = *(const float4*)(arow + a_half + 4 * j);
    {
        __nv_bfloat16* dh = sA + a_row * SAB_STR + a_half;
        __nv_bfloat16* dl = dh + SAB_PL;
        #pragma unroll
        for (int j = 0; j < 4; j++) {
            __nv_bfloat16 h0 = __float2bfloat16(areg[j].x);
            __nv_bfloat16 h1 = __float2bfloat16(areg[j].y);
            __nv_bfloat16 h2 = __float2bfloat16(areg[j].z);
            __nv_bfloat16 h3 = __float2bfloat16(areg[j].w);
            __nv_bfloat16 l0 = __float2bfloat16(areg[j].x - __bfloat162float(h0));
            __nv_bfloat16 l1 = __float2bfloat16(areg[j].y - __bfloat162float(h1));
            __nv_bfloat16 l2 = __float2bfloat16(areg[j].z - __bfloat162float(h2));
            __nv_bfloat16 l3 = __float2bfloat16(areg[j].w - __bfloat162float(h3));
            *(uint2*)(dh + 4 * j) = make_uint2(pk2(h0, h1), pk2(h2, h3));
            *(uint2*)(dl + 4 * j) = make_uint2(pk2(l0, l1), pk2(l2, l3));
        }
    }
    __syncthreads();

    float acc[4][4][4];
    #pragma unroll
    for (int mf = 0; mf < 4; mf++)
        #pragma unroll
        for (int nf = 0; nf < 4; nf++)
            #pragma unroll
            for (int c = 0; c < 4; c++) acc[mf][nf][c] = 0.0f;

    const int a_m0 = wm * 64;
    const int b_n0 = wn * 32;

    for (int kt = 0; kt < 4; kt++) {
        if (kt < 3) {
            #pragma unroll
            for (int j = 0; j < 4; j++)
                areg[j] = *(const float4*)(arow + (kt + 1) * 32 + a_half + 4 * j);
        }
        const __nv_bfloat16* Ahp = sA + (kt & 1) * (2 * SAB_PL);

        #pragma unroll
        for (int st = 0; st < 2; st++) {
            const int kloc  = st * 16;
            const int kglob = kt * 32 + kloc;
            unsigned ah[4][4], al[4][4];
            #pragma unroll
            for (int mf = 0; mf < 4; mf++) {
                const __nv_bfloat16* pa_ = Ahp + (a_m0 + 16 * mf + lt8 + lr) * SAB_STR + kloc + lk8;
                ldsm_x4(ah[mf], s2u(pa_));
                ldsm_x4(al[mf], s2u(pa_ + SAB_PL));
            }
            unsigned bh[4][2], bl[4][2];
            #pragma unroll
            for (int p = 0; p < 2; p++) {
                const __nv_bfloat16* pb = sBh + (b_n0 + 16 * p + bnoff + lr) * SBB_STR + kglob + bk8;
                unsigned t[4];
                ldsm_x4(t, s2u(pb));
                bh[2*p][0] = t[0]; bh[2*p][1] = t[1];
                bh[2*p+1][0] = t[2]; bh[2*p+1][1] = t[3];
                ldsm_x4(t, s2u(pb + SBB_PL));
                bl[2*p][0] = t[0]; bl[2*p][1] = t[1];
                bl[2*p+1][0] = t[2]; bl[2*p+1][1] = t[3];
            }
            #pragma unroll
            for (int nf = 0; nf < 4; nf++)
                #pragma unroll
                for (int mf = 0; mf < 4; mf++)
                    mma_bf16(acc[mf][nf], ah[mf], bl[nf][0], bl[nf][1]);
            #pragma unroll
            for (int nf = 0; nf < 4; nf++)
                #pragma unroll
                for (int mf = 0; mf < 4; mf++)
                    mma_bf16(acc[mf][nf], al[mf], bh[nf][0], bh[nf][1]);
            #pragma unroll
            for (int nf = 0; nf < 4; nf++)
                #pragma unroll
                for (int mf = 0; mf < 4; mf++)
                    mma_bf16(acc[mf][nf], ah[mf], bh[nf][0], bh[nf][1]);
        }

        if (kt < 3) {
            __nv_bfloat16* dh = sA + ((kt + 1) & 1) * (2 * SAB_PL) + a_row * SAB_STR + a_half;
            __nv_bfloat16* dl = dh + SAB_PL;
            #pragma unroll
            for (int j = 0; j < 4; j++) {
                __nv_bfloat16 h0 = __float2bfloat16(areg[j].x);
                __nv_bfloat16 h1 = __float2bfloat16(areg[j].y);
                __nv_bfloat16 h2 = __float2bfloat16(areg[j].z);
                __nv_bfloat16 h3 = __float2bfloat16(areg[j].w);
                __nv_bfloat16 l0 = __float2bfloat16(areg[j].x - __bfloat162float(h0));
                __nv_bfloat16 l1 = __float2bfloat16(areg[j].y - __bfloat162float(h1));
                __nv_bfloat16 l2 = __float2bfloat16(areg[j].z - __bfloat162float(h2));
                __nv_bfloat16 l3 = __float2bfloat16(areg[j].w - __bfloat162float(h3));
                *(uint2*)(dh + 4 * j) = make_uint2(pk2(h0, h1), pk2(h2, h3));
                *(uint2*)(dl + 4 * j) = make_uint2(pk2(l0, l1), pk2(l2, l3));
            }
            __syncthreads();
        }
    }

    // ---- epilogue ----
    #pragma unroll
    for (int mf = 0; mf < 4; mf++) {
        int row0 = by * 128 + a_m0 + mf * 16 + g4;
        #pragma unroll
        for (int nf = 0; nf < 4; nf++) {
            int ncol = b_n0 + nf * 8 + 2 * t4;
            float bb0 = bias[nblk + ncol];
            float bb1 = bias[nblk + ncol + 1];
            float v00 = (acc[mf][nf][0] + bb0) * alpha;
            float v01 = (acc[mf][nf][1] + bb1) * alpha;
            float v10 = (acc[mf][nf][2] + bb0) * alpha;
            float v11 = (acc[mf][nf][3] + bb1) * alpha;
            if (DST == 0) {
                *(unsigned*)(g_Qh + (size_t)row0 * 128 + ncol)       = h2pk(v00, v01);
                *(unsigned*)(g_Qh + (size_t)(row0 + 8) * 128 + ncol) = h2pk(v10, v11);
            } else {
                if (blockIdx.x == 0) {
                    *(unsigned*)(g_Kwh + (size_t)row0 * 128 + ncol)       = h2pk(v00, v01);
                    *(unsigned*)(g_Kwh + (size_t)(row0 + 8) * 128 + ncol) = h2pk(v10, v11);
                } else {
                    __half h00 = __float2half_rn(v00), h01 = __float2half_rn(v01);
                    __half h10 = __float2half_rn(v10), h11 = __float2half_rn(v11);
                    __half2 p0(h00, h01), p1(h10, h11);
                    *(unsigned*)(g_Vwh + (size_t)row0 * 128 + ncol)       = *(unsigned*)&p0;
                    *(unsigned*)(g_Vwh + (size_t)(row0 + 8) * 128 + ncol) = *(unsigned*)&p1;
                    *(unsigned*)(g_Vwl + (size_t)row0 * 128 + ncol) =
                        h2pk(v00 - __half2float(h00), v01 - __half2float(h01));
                    *(unsigned*)(g_Vwl + (size_t)(row0 + 8) * 128 + ncol) =
                        h2pk(v10 - __half2float(h10), v11 - __half2float(h11));
                }
            }
        }
    }
}

// ---------------- bias gather ----------------
__global__ void bias_build_kernel(const float* __restrict__ table,
                                  const int* __restrict__ ridx)
{
    int idx = blockIdx.x * 256 + threadIdx.x;
    if (idx < HEADS * NGT * NTOK) {
        int h  = idx / (NGT * NTOK);
        int ij = idx - h * (NGT * NTOK);
        g_bias[idx] = table[ridx[ij] * HEADS + h];
    }
}

// =====================================================================
// Window attention: 512 threads, 16 warps = (head, row-quarter).
// =====================================================================
#define WH_STR 136
#define WPLANE (64 * WH_STR)
#define WIN_SMEM (4 * WPLANE * 2)        // 69632 bytes

__global__ void __launch_bounds__(512)
win_attn_mma(const float* __restrict__ mask, float* __restrict__ out)
{
    extern __shared__ __half smh[];
    __half* sQ  = smh;
    __half* sK  = smh + WPLANE;
    __half* sVh = smh + 2 * WPLANE;
    __half* sVl = smh + 3 * WPLANE;

    const int w    = blockIdx.x;
    const int tid  = threadIdx.x;
    const int wid  = tid >> 5;
    const int h    = wid & 3;
    const int qtr  = wid >> 2;
    const int lane = tid & 31;
    const int g4   = lane >> 2;
    const int t4   = lane & 3;

    {
        uint4 z = make_uint4(0, 0, 0, 0);
        uint4* zq = (uint4*)(sQ + 49 * WH_STR);
        uint4* zk = (uint4*)(sK + 50 * WH_STR);
        uint4* zh = (uint4*)(sVh + 50 * WH_STR);
        uint4* zl = (uint4*)(sVl + 50 * WH_STR);
        for (int i = tid; i < 255; i += 512) zq[i] = z;
        for (int i = tid; i < 238; i += 512) { zk[i] = z; zh[i] = z; zl[i] = z; }
    }

    for (int idx = tid; idx < 49 * 16; idx += 512) {
        int r = idx >> 4, c = idx & 15;
        ((uint4*)(sQ + r * WH_STR))[c] =
            ((const uint4*)(g_Qh + (size_t)(w * NGT + r) * CDIM))[c];
    }
    for (int idx = tid; idx < 50 * 16; idx += 512) {
        int r = idx >> 4, c = idx & 15;
        size_t base = (size_t)(w * NTOK + r) * CDIM;
        ((uint4*)(sK  + r * WH_STR))[c] = ((const uint4*)(g_Kwh + base))[c];
        ((uint4*)(sVh + r * WH_STR))[c] = ((const uint4*)(g_Vwh + base))[c];
        ((uint4*)(sVl + r * WH_STR))[c] = ((const uint4*)(g_Vwl + base))[c];
    }
    __syncthreads();

    // ---- S = Q K^T ----
    float sacc[7][4];
    #pragma unroll
    for (int nf = 0; nf < 7; nf++)
        #pragma unroll
        for (int c = 0; c < 4; c++) sacc[nf][c] = 0.0f;

    #pragma unroll
    for (int ks = 0; ks < 2; ks++) {
        const int kc = h * HD + ks * 16 + 2 * t4;
        unsigned a[4];
        const __half* ap = sQ + (16 * qtr + g4) * WH_STR + kc;
        a[0] = *(const unsigned*)(ap);
        a[1] = *(const unsigned*)(ap + 8 * WH_STR);
        a[2] = *(const unsigned*)(ap + 8);
        a[3] = *(const unsigned*)(ap + 8 * WH_STR + 8);
        #pragma unroll
        for (int nf = 0; nf < 7; nf++) {
            const __half* bp = sK + (8 * nf + g4) * WH_STR + kc;
            unsigned b0 = *(const unsigned*)(bp);
            unsigned b1 = *(const unsigned*)(bp + 8);
            mma_f16(sacc[nf], a, b0, b1);
        }
    }

    // ---- bias + mask + softmax ----
    const float* bptr = g_bias + h * (NGT * NTOK);
    const float* mptr = mask + (size_t)(w & 63) * (NGT * NTOK);
    const int i0 = 16 * qtr + g4;
    const int i1 = i0 + 8;
    float m0 = -1e30f, m1 = -1e30f;
    #pragma unroll
    for (int nf = 0; nf < 7; nf++) {
        const int j0 = 8 * nf + 2 * t4;
        const int j1 = j0 + 1;
        float s0 = (i0 < NGT && j0 < NTOK) ? sacc[nf][0] + bptr[i0 * 50 + j0] + mptr[i0 * 50 + j0] : -1e30f;
        float s1 = (i0 < NGT && j1 < NTOK) ? sacc[nf][1] + bptr[i0 * 50 + j1] + mptr[i0 * 50 + j1] : -1e30f;
        float s2 = (i1 < NGT && j0 < NTOK) ? sacc[nf][2] + bptr[i1 * 50 + j0] + mptr[i1 * 50 + j0] : -1e30f;
        float s3 = (i1 < NGT && j1 < NTOK) ? sacc[nf][3] + bptr[i1 * 50 + j1] + mptr[i1 * 50 + j1] : -1e30f;
        sacc[nf][0] = s0; sacc[nf][1] = s1;
        sacc[nf][2] = s2; sacc[nf][3] = s3;
        m0 = fmaxf(m0, fmaxf(s0, s1));
        m1 = fmaxf(m1, fmaxf(s2, s3));
    }
    m0 = fmaxf(m0, __shfl_xor_sync(0xffffffffu, m0, 1));
    m0 = fmaxf(m0, __shfl_xor_sync(0xffffffffu, m0, 2));
    m1 = fmaxf(m1, __shfl_xor_sync(0xffffffffu, m1, 1));
    m1 = fmaxf(m1, __shfl_xor_sync(0xffffffffu, m1, 2));
    float r0 = 0.0f, r1 = 0.0f;
    #pragma unroll
    for (int nf = 0; nf < 7; nf++) {
        float p0 = __expf(sacc[nf][0] - m0);
        float p1 = __expf(sacc[nf][1] - m0);
        float p2 = __expf(sacc[nf][2] - m1);
        float p3 = __expf(sacc[nf][3] - m1);
        sacc[nf][0] = p0; sacc[nf][1] = p1;
        sacc[nf][2] = p2; sacc[nf][3] = p3;
        r0 += p0 + p1;
        r1 += p2 + p3;
    }
    r0 += __shfl_xor_sync(0xffffffffu, r0, 1);
    r0 += __shfl_xor_sync(0xffffffffu, r0, 2);
    r1 += __shfl_xor_sync(0xffffffffu, r1, 1);
    r1 += __shfl_xor_sync(0xffffffffu, r1, 2);

    // ---- pack P into fp16 A-fragments ----
    unsigned pa[4][4];
    #pragma unroll
    for (int ks = 0; ks < 3; ks++) {
        pa[ks][0] = h2pk(sacc[2*ks][0],   sacc[2*ks][1]);
        pa[ks][1] = h2pk(sacc[2*ks][2],   sacc[2*ks][3]);
        pa[ks][2] = h2pk(sacc[2*ks+1][0], sacc[2*ks+1][1]);
        pa[ks][3] = h2pk(sacc[2*ks+1][2], sacc[2*ks+1][3]);
    }
    pa[3][0] = h2pk(sacc[6][0], sacc[6][1]);
    pa[3][1] = h2pk(sacc[6][2], sacc[6][3]);
    pa[3][2] = 0u;
    pa[3][3] = 0u;

    // ---- O = P V ----
    float oacc[4][4];
    #pragma unroll
    for (int nf = 0; nf < 4; nf++)
        #pragma unroll
        for (int c = 0; c < 4; c++) oacc[nf][c] = 0.0f;

    const int lr    = lane & 7;
    const int vbk   = ((lane >> 3) & 1) * 8;
    const int vnoff = ((lane >> 4) & 1) * 8;

    #pragma unroll
    for (int ks = 0; ks < 4; ks++) {
        unsigned bh[4][2], bl[4][2];
        #pragma unroll
        for (int p = 0; p < 2; p++) {
            const __half* vp = sVh + (ks * 16 + vbk + lr) * WH_STR + h * HD + 16 * p + vnoff;
            unsigned t[4];
            ldsm_x4_t(t, s2u(vp));
            bh[2*p][0] = t[0]; bh[2*p][1] = t[1];
            bh[2*p+1][0] = t[2]; bh[2*p+1][1] = t[3];
            ldsm_x4_t(t, s2u(vp + WPLANE));
            bl[2*p][0] = t[0]; bl[2*p][1] = t[1];
            bl[2*p+1][0] = t[2]; bl[2*p+1][1] = t[3];
        }
        #pragma unroll
        for (int nf = 0; nf < 4; nf++)
            mma_f16(oacc[nf], pa[ks], bh[nf][0], bh[nf][1]);
        #pragma unroll
        for (int nf = 0; nf < 4; nf++)
            mma_f16(oacc[nf], pa[ks], bl[nf][0], bl[nf][1]);
    }

    // ---- normalize + store ----
    const float inv0 = 1.0f / r0;
    const float inv1 = 1.0f / r1;
    #pragma unroll
    for (int nf = 0; nf < 4; nf++) {
        const int col = h * HD + 8 * nf + 2 * t4;
        if (i0 < NGT) {
            float2 v; v.x = oacc[nf][0] * inv0; v.y = oacc[nf][1] * inv0;
            *(float2*)(out + (size_t)(w * NGT + i0) * CDIM + col) = v;
        }
        if (i1 < NGT) {
            float2 v; v.x = oacc[nf][2] * inv1; v.y = oacc[nf][3] * inv1;
            *(float2*)(out + (size_t)(w * NGT + i1) * CDIM + col) = v;
        }
    }
}

// =====================================================================
// Global-token attention, GEMM-free:
//   q = xavg@Wq + bq (not scaled); u = W_k[:,hs] q_hs; c0 = b_k[hs]·q_hs
//   logits_m = xtotal_m·u + c0 ; p = softmax(logits)
//   t = (p @ xtotal)/sum ; out = t@W_v[:,hs] + b_v[hs]
// One block per (b, h). 512 threads.
// =====================================================================
__global__ void __launch_bounds__(512)
glob_attn2(const float* __restrict__ xtotal, const float* __restrict__ xavg,
           const float* __restrict__ Wq, const float* __restrict__ bq,
           const float* __restrict__ Wkv, const float* __restrict__ bkv,
           float* __restrict__ out)
{
    const int b = blockIdx.x;
    const int h = blockIdx.y;
    const int tid  = threadIdx.x;
    const int warp = tid >> 5;
    const int lane = tid & 31;

    __shared__ float sq[128];          // q_avg (full 128)
    __shared__ float su[128];          // u vector
    __shared__ float sc0;
    __shared__ float slog[NTPAT];
    __shared__ float red[512];
    __shared__ float stp[16][128];     // per-warp partial t
    __shared__ float st[128];

    // q = xavg @ Wq + bq
    if (tid < 128) {
        float acc = bq[tid];
        const float* xr = xavg + (size_t)b * CDIM;
        #pragma unroll 4
        for (int c = 0; c < CDIM; c++)
            acc += xr[c] * Wq[c * CDIM + tid];
        sq[tid] = acc;
    }
    __syncthreads();

    // u[c] = sum_{j in head} Wkv[c][h*32+j] * q[h*32+j]
    if (tid < 128) {
        float acc = 0.0f;
        const float* wr = Wkv + (size_t)tid * 256 + h * HD;
        const float* qh = sq + h * HD;
        #pragma unroll 8
        for (int j = 0; j < HD; j++)
            acc += wr[j] * qh[j];
        su[tid] = acc;
    }
    if (warp == 15) {   // c0 = b_k[hs] . q_hs
        float t = bkv[h * HD + lane] * sq[h * HD + lane];
        #pragma unroll
        for (int o = 16; o; o >>= 1) t += __shfl_down_sync(0xffffffffu, t, o);
        if (lane == 0) sc0 = t;
    }
    __syncthreads();

    // logits
    const float* Xb = xtotal + (size_t)b * NTPAT * CDIM;
    float u0 = su[lane * 4 + 0], u1 = su[lane * 4 + 1];
    float u2 = su[lane * 4 + 2], u3 = su[lane * 4 + 3];
    const float c0 = sc0;
    for (int m = warp; m < NTPAT; m += 16) {
        float4 x4 = *(const float4*)(Xb + (size_t)m * CDIM + lane * 4);
        float p = x4.x * u0 + x4.y * u1 + x4.z * u2 + x4.w * u3;
        #pragma unroll
        for (int o = 16; o; o >>= 1) p += __shfl_down_sync(0xffffffffu, p, o);
        if (lane == 0) slog[m] = p + c0;
    }
    __syncthreads();

    // softmax
    float mx = -1e30f;
    for (int m = tid; m < NTPAT; m += 512) mx = fmaxf(mx, slog[m]);
    red[tid] = mx; __syncthreads();
    for (int s = 256; s; s >>= 1) { if (tid < s) red[tid] = fmaxf(red[tid], red[tid + s]); __syncthreads(); }
    mx = red[0]; __syncthreads();

    float sum = 0.0f;
    for (int m = tid; m < NTPAT; m += 512) {
        float e = expf(slog[m] - mx);
        slog[m] = e;
        sum += e;
    }
    red[tid] = sum; __syncthreads();
    for (int s = 256; s; s >>= 1) { if (tid < s) red[tid] += red[tid + s]; __syncthreads(); }
    sum = red[0];
    __syncthreads();

    // t = sum_m p_m * x_m  (per-warp partials, 4 cols per lane)
    float a0 = 0.0f, a1 = 0.0f, a2 = 0.0f, a3 = 0.0f;
    for (int m = warp; m < NTPAT; m += 16) {
        float p = slog[m];
        float4 x4 = *(const float4*)(Xb + (size_t)m * CDIM + lane * 4);
        a0 += p * x4.x; a1 += p * x4.y; a2 += p * x4.z; a3 += p * x4.w;
    }
    stp[warp][lane * 4 + 0] = a0;
    stp[warp][lane * 4 + 1] = a1;
    stp[warp][lane * 4 + 2] = a2;
    stp[warp][lane * 4 + 3] = a3;
    __syncthreads();
    if (tid < 128) {
        float t = 0.0f;
        #pragma unroll
        for (int w2 = 0; w2 < 16; w2++) t += stp[w2][tid];
        st[tid] = t / sum;
    }
    __syncthreads();

    // out[d] = b_v[hs+d] + sum_c t[c] * W_v[c][hs+d]
    if (tid < 32) {
        float o = bkv[128 + h * HD + tid];
        const float* wv = Wkv + 128 + h * HD + tid;
        #pragma unroll 4
        for (int c = 0; c < CDIM; c++)
            o += st[c] * wv[(size_t)c * 256];
        out[(size_t)b * CDIM + h * HD + tid] = o;
    }
}

// ---------------- launch ----------------
extern "C" void kernel_launch(void* const* d_in, const int* in_sizes, int n_in,
                              void* d_out, int out_size)
{
    const float* x      = (const float*)d_in[0];
    const float* xtotal = (const float*)d_in[1];
    const float* xavg   = (const float*)d_in[2];
    const float* mask   = (const float*)d_in[3];
    const float* Wq     = (const float*)d_in[4];
    const float* bq     = (const float*)d_in[5];
    const float* Wkv    = (const float*)d_in[6];
    const float* bkv    = (const float*)d_in[7];
    const float* btab   = (const float*)d_in[8];
    const int*   ridx   = (const int*)d_in[9];

    float* out     = (float*)d_out;
    float* out_avg = out + (size_t)200704u * 128u;

    static cudaStream_t s2 = nullptr;
    static cudaEvent_t evF = nullptr, evJ = nullptr;
    if (s2 == nullptr) {
        cudaStreamCreateWithFlags(&s2, cudaStreamNonBlocking);
        cudaEventCreateWithFlags(&evF, cudaEventDisableTiming);
        cudaEventCreateWithFlags(&evJ, cudaEventDisableTiming);
        cudaFuncSetAttribute(bf16_gemm<0, 0>, cudaFuncAttributeMaxDynamicSharedMemorySize, GEMM_SMEM);
        cudaFuncSetAttribute(bf16_gemm<1, 1>, cudaFuncAttributeMaxDynamicSharedMemorySize, GEMM_SMEM);
        cudaFuncSetAttribute(win_attn_mma, cudaFuncAttributeMaxDynamicSharedMemorySize, WIN_SMEM);
    }

    // fork: global path (GEMM-free) on s2
    cudaEventRecord(evF, 0);
    cudaStreamWaitEvent(s2, evF, 0);
    glob_attn2<<<dim3(BIMG, HEADS), 512, 0, s2>>>(xtotal, xavg, Wq, bq, Wkv, bkv, out_avg);
    cudaEventRecord(evJ, s2);

    // window path on the default stream
    bias_build_kernel<<<(HEADS * NGT * NTOK + 255) / 256, 256>>>(btab, ridx);
    bf16_gemm<0, 0><<<dim3(1, 1568), 256, GEMM_SMEM>>>(x, nullptr, Wq, bq, 128, WQ_SCALE);
    bf16_gemm<1, 1><<<dim3(2, 1600), 256, GEMM_SMEM>>>(x, xavg, Wkv, bkv, 256, 1.0f);
    win_attn_mma<<<NWIN, 512, WIN_SMEM>>>(mask, out);

    // join
    cudaStreamWaitEvent(0, evJ, 0);
}

// round 12
// speedup vs baseline: 1.2076x; 1.2076x over previous
#include <cuda_runtime.h>
#include <cuda_bf16.h>
#include <cuda_fp16.h>

// ---------------- problem dims ----------------
#define NWIN   4096
#define NGT    49
#define NTOK   50
#define CDIM   128
#define HEADS  4
#define HD     32
#define BIMG   64
#define NTPAT  3136
#define WQ_SCALE 0.17677669529663687f   // 32^-0.5

// ---------------- device scratch ----------------
__device__ __half g_Qh [200704u * 128u];
__device__ __half g_Kwh[204800u * 128u];
__device__ __half g_Vwh[204800u * 128u];
__device__ __half g_Vwl[204800u * 128u];
__device__ float  g_bias[HEADS * NGT * NTOK];

// ---------------- helpers ----------------
__device__ __forceinline__ void mma_bf16(float* c, const unsigned* a,
                                         unsigned b0, unsigned b1)
{
    asm volatile("mma.sync.aligned.m16n8k16.row.col.f32.bf16.bf16.f32 "
                 "{%0,%1,%2,%3}, {%4,%5,%6,%7}, {%8,%9}, {%0,%1,%2,%3};"
                 : "+f"(c[0]), "+f"(c[1]), "+f"(c[2]), "+f"(c[3])
                 : "r"(a[0]), "r"(a[1]), "r"(a[2]), "r"(a[3]), "r"(b0), "r"(b1));
}
__device__ __forceinline__ void mma_f16(float* c, const unsigned* a,
                                        unsigned b0, unsigned b1)
{
    asm volatile("mma.sync.aligned.m16n8k16.row.col.f32.f16.f16.f32 "
                 "{%0,%1,%2,%3}, {%4,%5,%6,%7}, {%8,%9}, {%0,%1,%2,%3};"
                 : "+f"(c[0]), "+f"(c[1]), "+f"(c[2]), "+f"(c[3])
                 : "r"(a[0]), "r"(a[1]), "r"(a[2]), "r"(a[3]), "r"(b0), "r"(b1));
}
__device__ __forceinline__ void ldsm_x4(unsigned* r, unsigned addr) {
    asm volatile("ldmatrix.sync.aligned.m8n8.x4.shared.b16 {%0,%1,%2,%3}, [%4];"
                 : "=r"(r[0]), "=r"(r[1]), "=r"(r[2]), "=r"(r[3]) : "r"(addr));
}
__device__ __forceinline__ void ldsm_x4_t(unsigned* r, unsigned addr) {
    asm volatile("ldmatrix.sync.aligned.m8n8.x4.trans.shared.b16 {%0,%1,%2,%3}, [%4];"
                 : "=r"(r[0]), "=r"(r[1]), "=r"(r[2]), "=r"(r[3]) : "r"(addr));
}
__device__ __forceinline__ unsigned s2u(const void* p) {
    return (unsigned)__cvta_generic_to_shared(p);
}
__device__ __forceinline__ unsigned pk2(__nv_bfloat16 a, __nv_bfloat16 b) {
    __nv_bfloat162 t(a, b);
    return *reinterpret_cast<unsigned*>(&t);
}
__device__ __forceinline__ unsigned h2pk(float a, float b) {
    __half2 t = __floats2half2_rn(a, b);
    return *reinterpret_cast<unsigned*>(&t);
}

// =====================================================================
// Split-BF16 projection GEMM (window path).
// =====================================================================
#define SBB_STR 136
#define SAB_STR 40
#define SBB_PL  (128 * SBB_STR)
#define SAB_PL  (128 * SAB_STR)
#define GEMM_SMEM ((2 * SBB_PL + 4 * SAB_PL) * 2)   // 110592 bytes

template<int GATHER, int DST>
__global__ void __launch_bounds__(256, 2)
bf16_gemm(const float* __restrict__ A, const float* __restrict__ Aavg,
          const float* __restrict__ W, const float* __restrict__ bias,
          int N, float alpha)
{
    extern __shared__ __nv_bfloat16 sm[];
    __nv_bfloat16* sBh = sm;
    __nv_bfloat16* sBl = sm + SBB_PL;
    __nv_bfloat16* sA  = sm + 2 * SBB_PL;

    const int tid  = threadIdx.x;
    const int lane = tid & 31;
    const int warp = tid >> 5;
    const int wm   = warp >> 2;
    const int wn   = warp & 3;
    const int g4   = lane >> 2;
    const int t4   = lane & 3;
    const int nblk = blockIdx.x * 128;
    const int by   = blockIdx.y;

    const int lr    = lane & 7;
    const int lt8   = ((lane >> 3) & 1) * 8;
    const int lk8   = (lane >> 4) * 8;
    const int bnoff = ((lane >> 4) & 1) * 8;
    const int bk8   = ((lane >> 3) & 1) * 8;

    const int a_row  = tid >> 1;
    const int a_half = (tid & 1) * 16;
    const int m = by * 128 + a_row;
    const float* arow;
    if (GATHER) {
        int w  = m / NTOK;
        int rr = m - w * NTOK;
        arow = (rr < NGT) ? (A    + (size_t)(w * NGT + rr) * CDIM)
                          : (Aavg + (size_t)(w >> 6)       * CDIM);
    } else {
        arow = A + (size_t)m * CDIM;
    }

    // ---- B panel ----
    {
        const int nloc  = (warp & 3) * 32 + lane;
        const int kbase = (warp >> 2) * 64;
        const float* wp = W + nblk + nloc;
        #pragma unroll
        for (int kg = 0; kg < 16; kg++) {
            const int k = kbase + kg * 4;
            float v0 = wp[(size_t)(k + 0) * N];
            float v1 = wp[(size_t)(k + 1) * N];
            float v2 = wp[(size_t)(k + 2) * N];
            float v3 = wp[(size_t)(k + 3) * N];
            __nv_bfloat16 h0 = __float2bfloat16(v0);
            __nv_bfloat16 h1 = __float2bfloat16(v1);
            __nv_bfloat16 h2 = __float2bfloat16(v2);
            __nv_bfloat16 h3 = __float2bfloat16(v3);
            __nv_bfloat16 l0 = __float2bfloat16(v0 - __bfloat162float(h0));
            __nv_bfloat16 l1 = __float2bfloat16(v1 - __bfloat162float(h1));
            __nv_bfloat16 l2 = __float2bfloat16(v2 - __bfloat162float(h2));
            __nv_bfloat16 l3 = __float2bfloat16(v3 - __bfloat162float(h3));
            *(uint2*)(sBh + nloc * SBB_STR + k) = make_uint2(pk2(h0, h1), pk2(h2, h3));
            *(uint2*)(sBl + nloc * SBB_STR + k) = make_uint2(pk2(l0, l1), pk2(l2, l3));
        }
    }

    // ---- A prologue ----
    float4 areg[4];
    #pragma unroll
    for (int j = 0; j < 4; j++)
        areg[j] = *(const float4*)(arow + a_half + 4 * j);
    {
        __nv_bfloat16* dh = sA + a_row * SAB_STR + a_half;
        __nv_bfloat16* dl = dh + SAB_PL;
        #pragma unroll
        for (int j = 0; j < 4; j++) {
            __nv_bfloat16 h0 = __float2bfloat16(areg[j].x);
            __nv_bfloat16 h1 = __float2bfloat16(areg[j].y);
            __nv_bfloat16 h2 = __float2bfloat16(areg[j].z);
            __nv_bfloat16 h3 = __float2bfloat16(areg[j].w);
            __nv_bfloat16 l0 = __float2bfloat16(areg[j].x - __bfloat162float(h0));
            __nv_bfloat16 l1 = __float2bfloat16(areg[j].y - __bfloat162float(h1));
            __nv_bfloat16 l2 = __float2bfloat16(areg[j].z - __bfloat162float(h2));
            __nv_bfloat16 l3 = __float2bfloat16(areg[j].w - __bfloat162float(h3));
            *(uint2*)(dh + 4 * j) = make_uint2(pk2(h0, h1), pk2(h2, h3));
            *(uint2*)(dl + 4 * j) = make_uint2(pk2(l0, l1), pk2(l2, l3));
        }
    }
    __syncthreads();

    float acc[4][4][4];
    #pragma unroll
    for (int mf = 0; mf < 4; mf++)
        #pragma unroll
        for (int nf = 0; nf < 4; nf++)
            #pragma unroll
            for (int c = 0; c < 4; c++) acc[mf][nf][c] = 0.0f;

    const int a_m0 = wm * 64;
    const int b_n0 = wn * 32;

    for (int kt = 0; kt < 4; kt++) {
        if (kt < 3) {
            #pragma unroll
            for (int j = 0; j < 4; j++)
                areg[j] = *(const float4*)(arow + (kt + 1) * 32 + a_half + 4 * j);
        }
        const __nv_bfloat16* Ahp = sA + (kt & 1) * (2 * SAB_PL);

        #pragma unroll
        for (int st = 0; st < 2; st++) {
            const int kloc  = st * 16;
            const int kglob = kt * 32 + kloc;
            unsigned ah[4][4], al[4][4];
            #pragma unroll
            for (int mf = 0; mf < 4; mf++) {
                const __nv_bfloat16* pa_ = Ahp + (a_m0 + 16 * mf + lt8 + lr) * SAB_STR + kloc + lk8;
                ldsm_x4(ah[mf], s2u(pa_));
                ldsm_x4(al[mf], s2u(pa_ + SAB_PL));
            }
            unsigned bh[4][2], bl[4][2];
            #pragma unroll
            for (int p = 0; p < 2; p++) {
                const __nv_bfloat16* pb = sBh + (b_n0 + 16 * p + bnoff + lr) * SBB_STR + kglob + bk8;
                unsigned t[4];
                ldsm_x4(t, s2u(pb));
                bh[2*p][0] = t[0]; bh[2*p][1] = t[1];
                bh[2*p+1][0] = t[2]; bh[2*p+1][1] = t[3];
                ldsm_x4(t, s2u(pb + SBB_PL));
                bl[2*p][0] = t[0]; bl[2*p][1] = t[1];
                bl[2*p+1][0] = t[2]; bl[2*p+1][1] = t[3];
            }
            #pragma unroll
            for (int nf = 0; nf < 4; nf++)
                #pragma unroll
                for (int mf = 0; mf < 4; mf++)
                    mma_bf16(acc[mf][nf], ah[mf], bl[nf][0], bl[nf][1]);
            #pragma unroll
            for (int nf = 0; nf < 4; nf++)
                #pragma unroll
                for (int mf = 0; mf < 4; mf++)
                    mma_bf16(acc[mf][nf], al[mf], bh[nf][0], bh[nf][1]);
            #pragma unroll
            for (int nf = 0; nf < 4; nf++)
                #pragma unroll
                for (int mf = 0; mf < 4; mf++)
                    mma_bf16(acc[mf][nf], ah[mf], bh[nf][0], bh[nf][1]);
        }

        if (kt < 3) {
            __nv_bfloat16* dh = sA + ((kt + 1) & 1) * (2 * SAB_PL) + a_row * SAB_STR + a_half;
            __nv_bfloat16* dl = dh + SAB_PL;
            #pragma unroll
            for (int j = 0; j < 4; j++) {
                __nv_bfloat16 h0 = __float2bfloat16(areg[j].x);
                __nv_bfloat16 h1 = __float2bfloat16(areg[j].y);
                __nv_bfloat16 h2 = __float2bfloat16(areg[j].z);
                __nv_bfloat16 h3 = __float2bfloat16(areg[j].w);
                __nv_bfloat16 l0 = __float2bfloat16(areg[j].x - __bfloat162float(h0));
                __nv_bfloat16 l1 = __float2bfloat16(areg[j].y - __bfloat162float(h1));
                __nv_bfloat16 l2 = __float2bfloat16(areg[j].z - __bfloat162float(h2));
                __nv_bfloat16 l3 = __float2bfloat16(areg[j].w - __bfloat162float(h3));
                *(uint2*)(dh + 4 * j) = make_uint2(pk2(h0, h1), pk2(h2, h3));
                *(uint2*)(dl + 4 * j) = make_uint2(pk2(l0, l1), pk2(l2, l3));
            }
            __syncthreads();
        }
    }

    // ---- epilogue ----
    #pragma unroll
    for (int mf = 0; mf < 4; mf++) {
        int row0 = by * 128 + a_m0 + mf * 16 + g4;
        #pragma unroll
        for (int nf = 0; nf < 4; nf++) {
            int ncol = b_n0 + nf * 8 + 2 * t4;
            float bb0 = bias[nblk + ncol];
            float bb1 = bias[nblk + ncol + 1];
            float v00 = (acc[mf][nf][0] + bb0) * alpha;
            float v01 = (acc[mf][nf][1] + bb1) * alpha;
            float v10 = (acc[mf][nf][2] + bb0) * alpha;
            float v11 = (acc[mf][nf][3] + bb1) * alpha;
            if (DST == 0) {
                *(unsigned*)(g_Qh + (size_t)row0 * 128 + ncol)       = h2pk(v00, v01);
                *(unsigned*)(g_Qh + (size_t)(row0 + 8) * 128 + ncol) = h2pk(v10, v11);
            } else {
                if (blockIdx.x == 0) {
                    *(unsigned*)(g_Kwh + (size_t)row0 * 128 + ncol)       = h2pk(v00, v01);
                    *(unsigned*)(g_Kwh + (size_t)(row0 + 8) * 128 + ncol) = h2pk(v10, v11);
                } else {
                    __half h00 = __float2half_rn(v00), h01 = __float2half_rn(v01);
                    __half h10 = __float2half_rn(v10), h11 = __float2half_rn(v11);
                    __half2 p0(h00, h01), p1(h10, h11);
                    *(unsigned*)(g_Vwh + (size_t)row0 * 128 + ncol)       = *(unsigned*)&p0;
                    *(unsigned*)(g_Vwh + (size_t)(row0 + 8) * 128 + ncol) = *(unsigned*)&p1;
                    *(unsigned*)(g_Vwl + (size_t)row0 * 128 + ncol) =
                        h2pk(v00 - __half2float(h00), v01 - __half2float(h01));
                    *(unsigned*)(g_Vwl + (size_t)(row0 + 8) * 128 + ncol) =
                        h2pk(v10 - __half2float(h10), v11 - __half2float(h11));
                }
            }
        }
    }
}

// ---------------- bias gather ----------------
__global__ void bias_build_kernel(const float* __restrict__ table,
                                  const int* __restrict__ ridx)
{
    int idx = blockIdx.x * 256 + threadIdx.x;
    if (idx < HEADS * NGT * NTOK) {
        int h  = idx / (NGT * NTOK);
        int ij = idx - h * (NGT * NTOK);
        g_bias[idx] = table[ridx[ij] * HEADS + h];
    }
}

// =====================================================================
// Window attention: 512 threads, 16 warps = (head, row-quarter).
// =====================================================================
#define WH_STR 136
#define WPLANE (64 * WH_STR)
#define WIN_SMEM (4 * WPLANE * 2)        // 69632 bytes

__global__ void __launch_bounds__(512)
win_attn_mma(const float* __restrict__ mask, float* __restrict__ out)
{
    extern __shared__ __half smh[];
    __half* sQ  = smh;
    __half* sK  = smh + WPLANE;
    __half* sVh = smh + 2 * WPLANE;
    __half* sVl = smh + 3 * WPLANE;

    const int w    = blockIdx.x;
    const int tid  = threadIdx.x;
    const int wid  = tid >> 5;
    const int h    = wid & 3;
    const int qtr  = wid >> 2;
    const int lane = tid & 31;
    const int g4   = lane >> 2;
    const int t4   = lane & 3;

    {
        uint4 z = make_uint4(0, 0, 0, 0);
        uint4* zq = (uint4*)(sQ + 49 * WH_STR);
        uint4* zk = (uint4*)(sK + 50 * WH_STR);
        uint4* zh = (uint4*)(sVh + 50 * WH_STR);
        uint4* zl = (uint4*)(sVl + 50 * WH_STR);
        for (int i = tid; i < 255; i += 512) zq[i] = z;
        for (int i = tid; i < 238; i += 512) { zk[i] = z; zh[i] = z; zl[i] = z; }
    }

    for (int idx = tid; idx < 49 * 16; idx += 512) {
        int r = idx >> 4, c = idx & 15;
        ((uint4*)(sQ + r * WH_STR))[c] =
            ((const uint4*)(g_Qh + (size_t)(w * NGT + r) * CDIM))[c];
    }
    for (int idx = tid; idx < 50 * 16; idx += 512) {
        int r = idx >> 4, c = idx & 15;
        size_t base = (size_t)(w * NTOK + r) * CDIM;
        ((uint4*)(sK  + r * WH_STR))[c] = ((const uint4*)(g_Kwh + base))[c];
        ((uint4*)(sVh + r * WH_STR))[c] = ((const uint4*)(g_Vwh + base))[c];
        ((uint4*)(sVl + r * WH_STR))[c] = ((const uint4*)(g_Vwl + base))[c];
    }
    __syncthreads();

    // ---- S = Q K^T ----
    float sacc[7][4];
    #pragma unroll
    for (int nf = 0; nf < 7; nf++)
        #pragma unroll
        for (int c = 0; c < 4; c++) sacc[nf][c] = 0.0f;

    #pragma unroll
    for (int ks = 0; ks < 2; ks++) {
        const int kc = h * HD + ks * 16 + 2 * t4;
        unsigned a[4];
        const __half* ap = sQ + (16 * qtr + g4) * WH_STR + kc;
        a[0] = *(const unsigned*)(ap);
        a[1] = *(const unsigned*)(ap + 8 * WH_STR);
        a[2] = *(const unsigned*)(ap + 8);
        a[3] = *(const unsigned*)(ap + 8 * WH_STR + 8);
        #pragma unroll
        for (int nf = 0; nf < 7; nf++) {
            const __half* bp = sK + (8 * nf + g4) * WH_STR + kc;
            unsigned b0 = *(const unsigned*)(bp);
            unsigned b1 = *(const unsigned*)(bp + 8);
            mma_f16(sacc[nf], a, b0, b1);
        }
    }

    // ---- bias + mask + softmax ----
    const float* bptr = g_bias + h * (NGT * NTOK);
    const float* mptr = mask + (size_t)(w & 63) * (NGT * NTOK);
    const int i0 = 16 * qtr + g4;
    const int i1 = i0 + 8;
    float m0 = -1e30f, m1 = -1e30f;
    #pragma unroll
    for (int nf = 0; nf < 7; nf++) {
        const int j0 = 8 * nf + 2 * t4;
        const int j1 = j0 + 1;
        float s0 = (i0 < NGT && j0 < NTOK) ? sacc[nf][0] + bptr[i0 * 50 + j0] + mptr[i0 * 50 + j0] : -1e30f;
        float s1 = (i0 < NGT && j1 < NTOK) ? sacc[nf][1] + bptr[i0 * 50 + j1] + mptr[i0 * 50 + j1] : -1e30f;
        float s2 = (i1 < NGT && j0 < NTOK) ? sacc[nf][2] + bptr[i1 * 50 + j0] + mptr[i1 * 50 + j0] : -1e30f;
        float s3 = (i1 < NGT && j1 < NTOK) ? sacc[nf][3] + bptr[i1 * 50 + j1] + mptr[i1 * 50 + j1] : -1e30f;
        sacc[nf][0] = s0; sacc[nf][1] = s1;
        sacc[nf][2] = s2; sacc[nf][3] = s3;
        m0 = fmaxf(m0, fmaxf(s0, s1));
        m1 = fmaxf(m1, fmaxf(s2, s3));
    }
    m0 = fmaxf(m0, __shfl_xor_sync(0xffffffffu, m0, 1));
    m0 = fmaxf(m0, __shfl_xor_sync(0xffffffffu, m0, 2));
    m1 = fmaxf(m1, __shfl_xor_sync(0xffffffffu, m1, 1));
    m1 = fmaxf(m1, __shfl_xor_sync(0xffffffffu, m1, 2));
    float r0 = 0.0f, r1 = 0.0f;
    #pragma unroll
    for (int nf = 0; nf < 7; nf++) {
        float p0 = __expf(sacc[nf][0] - m0);
        float p1 = __expf(sacc[nf][1] - m0);
        float p2 = __expf(sacc[nf][2] - m1);
        float p3 = __expf(sacc[nf][3] - m1);
        sacc[nf][0] = p0; sacc[nf][1] = p1;
        sacc[nf][2] = p2; sacc[nf][3] = p3;
        r0 += p0 + p1;
        r1 += p2 + p3;
    }
    r0 += __shfl_xor_sync(0xffffffffu, r0, 1);
    r0 += __shfl_xor_sync(0xffffffffu, r0, 2);
    r1 += __shfl_xor_sync(0xffffffffu, r1, 1);
    r1 += __shfl_xor_sync(0xffffffffu, r1, 2);

    // ---- pack P into fp16 A-fragments ----
    unsigned pa[4][4];
    #pragma unroll
    for (int ks = 0; ks < 3; ks++) {
        pa[ks][0] = h2pk(sacc[2*ks][0],   sacc[2*ks][1]);
        pa[ks][1] = h2pk(sacc[2*ks][2],   sacc[2*ks][3]);
        pa[ks][2] = h2pk(sacc[2*ks+1][0], sacc[2*ks+1][1]);
        pa[ks][3] = h2pk(sacc[2*ks+1][2], sacc[2*ks+1][3]);
    }
    pa[3][0] = h2pk(sacc[6][0], sacc[6][1]);
    pa[3][1] = h2pk(sacc[6][2], sacc[6][3]);
    pa[3][2] = 0u;
    pa[3][3] = 0u;

    // ---- O = P V ----
    float oacc[4][4];
    #pragma unroll
    for (int nf = 0; nf < 4; nf++)
        #pragma unroll
        for (int c = 0; c < 4; c++) oacc[nf][c] = 0.0f;

    const int lr    = lane & 7;
    const int vbk   = ((lane >> 3) & 1) * 8;
    const int vnoff = ((lane >> 4) & 1) * 8;

    #pragma unroll
    for (int ks = 0; ks < 4; ks++) {
        unsigned bh[4][2], bl[4][2];
        #pragma unroll
        for (int p = 0; p < 2; p++) {
            const __half* vp = sVh + (ks * 16 + vbk + lr) * WH_STR + h * HD + 16 * p + vnoff;
            unsigned t[4];
            ldsm_x4_t(t, s2u(vp));
            bh[2*p][0] = t[0]; bh[2*p][1] = t[1];
            bh[2*p+1][0] = t[2]; bh[2*p+1][1] = t[3];
            ldsm_x4_t(t, s2u(vp + WPLANE));
            bl[2*p][0] = t[0]; bl[2*p][1] = t[1];
            bl[2*p+1][0] = t[2]; bl[2*p+1][1] = t[3];
        }
        #pragma unroll
        for (int nf = 0; nf < 4; nf++)
            mma_f16(oacc[nf], pa[ks], bh[nf][0], bh[nf][1]);
        #pragma unroll
        for (int nf = 0; nf < 4; nf++)
            mma_f16(oacc[nf], pa[ks], bl[nf][0], bl[nf][1]);
    }

    // ---- normalize + store ----
    const float inv0 = 1.0f / r0;
    const float inv1 = 1.0f / r1;
    #pragma unroll
    for (int nf = 0; nf < 4; nf++) {
        const int col = h * HD + 8 * nf + 2 * t4;
        if (i0 < NGT) {
            float2 v; v.x = oacc[nf][0] * inv0; v.y = oacc[nf][1] * inv0;
            *(float2*)(out + (size_t)(w * NGT + i0) * CDIM + col) = v;
        }
        if (i1 < NGT) {
            float2 v; v.x = oacc[nf][2] * inv1; v.y = oacc[nf][3] * inv1;
            *(float2*)(out + (size_t)(w * NGT + i1) * CDIM + col) = v;
        }
    }
}

// =====================================================================
// Global-token attention, GEMM-free, ALL 4 HEADS per block (one block
// per image): xtotal read once per pass, dotted with all u_h.
// smem (floats): sq 128 | su 4*128 | sc0 4 | slog 4*3136 | red 512 |
//                stp 16*512 | st 4*128  => 22404 floats = 89616 B
// =====================================================================
#define GA_SQ    0
#define GA_SU    128
#define GA_SC0   (GA_SU + 512)
#define GA_SLOG  (GA_SC0 + 4)
#define GA_RED   (GA_SLOG + 4 * NTPAT)
#define GA_STP   (GA_RED + 512)
#define GA_ST    (GA_STP + 16 * 512)
#define GA_SMEM  ((GA_ST + 512) * 4)

__global__ void __launch_bounds__(512)
glob_attn3(const float* __restrict__ xtotal, const float* __restrict__ xavg,
           const float* __restrict__ Wq, const float* __restrict__ bq,
           const float* __restrict__ Wkv, const float* __restrict__ bkv,
           float* __restrict__ out)
{
    extern __shared__ float gs[];
    float* sq   = gs + GA_SQ;
    float* su   = gs + GA_SU;     // [h][128]
    float* sc0  = gs + GA_SC0;    // [h]
    float* slog = gs + GA_SLOG;   // [h][NTPAT]
    float* red  = gs + GA_RED;    // [512]
    float* stp  = gs + GA_STP;    // [warp][512]  (h*128 + c)
    float* st   = gs + GA_ST;     // [h][128]

    const int b = blockIdx.x;
    const int tid  = threadIdx.x;
    const int warp = tid >> 5;
    const int lane = tid & 31;

    // q = xavg @ Wq + bq (full 128)
    if (tid < 128) {
        float acc = bq[tid];
        const float* xr = xavg + (size_t)b * CDIM;
        #pragma unroll 4
        for (int c = 0; c < CDIM; c++)
            acc += xr[c] * Wq[c * CDIM + tid];
        sq[tid] = acc;
    }
    __syncthreads();

    // u_h[c] = sum_j Wkv[c][h*32+j] * q[h*32+j]  (512 threads = 4h x 128c)
    {
        const int hh = tid >> 7;
        const int c  = tid & 127;
        float acc = 0.0f;
        const float* wr = Wkv + (size_t)c * 256 + hh * HD;
        const float* qh = sq + hh * HD;
        #pragma unroll 8
        for (int j = 0; j < HD; j++)
            acc += wr[j] * qh[j];
        su[hh * 128 + c] = acc;
    }
    if (warp < 4) {   // c0[h] = b_k[hs] . q_hs
        float t = bkv[warp * HD + lane] * sq[warp * HD + lane];
        #pragma unroll
        for (int o = 16; o; o >>= 1) t += __shfl_down_sync(0xffffffffu, t, o);
        if (lane == 0) sc0[warp] = t;
    }
    __syncthreads();

    // logits for all 4 heads, single pass over xtotal
    const float* Xb = xtotal + (size_t)b * NTPAT * CDIM;
    float u[4][4];
    #pragma unroll
    for (int hh = 0; hh < 4; hh++) {
        u[hh][0] = su[hh * 128 + lane * 4 + 0];
        u[hh][1] = su[hh * 128 + lane * 4 + 1];
        u[hh][2] = su[hh * 128 + lane * 4 + 2];
        u[hh][3] = su[hh * 128 + lane * 4 + 3];
    }
    for (int m = warp; m < NTPAT; m += 16) {
        float4 x4 = *(const float4*)(Xb + (size_t)m * CDIM + lane * 4);
        float p0 = x4.x * u[0][0] + x4.y * u[0][1] + x4.z * u[0][2] + x4.w * u[0][3];
        float p1 = x4.x * u[1][0] + x4.y * u[1][1] + x4.z * u[1][2] + x4.w * u[1][3];
        float p2 = x4.x * u[2][0] + x4.y * u[2][1] + x4.z * u[2][2] + x4.w * u[2][3];
        float p3 = x4.x * u[3][0] + x4.y * u[3][1] + x4.z * u[3][2] + x4.w * u[3][3];
        #pragma unroll
        for (int o = 16; o; o >>= 1) {
            p0 += __shfl_down_sync(0xffffffffu, p0, o);
            p1 += __shfl_down_sync(0xffffffffu, p1, o);
            p2 += __shfl_down_sync(0xffffffffu, p2, o);
            p3 += __shfl_down_sync(0xffffffffu, p3, o);
        }
        if (lane == 0) {
            slog[0 * NTPAT + m] = p0 + sc0[0];
            slog[1 * NTPAT + m] = p1 + sc0[1];
            slog[2 * NTPAT + m] = p2 + sc0[2];
            slog[3 * NTPAT + m] = p3 + sc0[3];
        }
    }
    __syncthreads();

    // softmax per head (loop, full block each)
    float invsum[4];
    #pragma unroll
    for (int hh = 0; hh < 4; hh++) {
        float* lg = slog + hh * NTPAT;
        float mx = -1e30f;
        for (int m = tid; m < NTPAT; m += 512) mx = fmaxf(mx, lg[m]);
        red[tid] = mx; __syncthreads();
        for (int s = 256; s; s >>= 1) { if (tid < s) red[tid] = fmaxf(red[tid], red[tid + s]); __syncthreads(); }
        mx = red[0]; __syncthreads();
        float sum = 0.0f;
        for (int m = tid; m < NTPAT; m += 512) {
            float e = expf(lg[m] - mx);
            lg[m] = e;
            sum += e;
        }
        red[tid] = sum; __syncthreads();
        for (int s = 256; s; s >>= 1) { if (tid < s) red[tid] += red[tid + s]; __syncthreads(); }
        invsum[hh] = 1.0f / red[0];
        __syncthreads();
    }

    // t_h = sum_m p_h[m] * x_m : one pass over xtotal, 16 accumulators
    float a[4][4];
    #pragma unroll
    for (int hh = 0; hh < 4; hh++)
        #pragma unroll
        for (int j = 0; j < 4; j++) a[hh][j] = 0.0f;
    for (int m = warp; m < NTPAT; m += 16) {
        float4 x4 = *(const float4*)(Xb + (size_t)m * CDIM + lane * 4);
        float p0 = slog[0 * NTPAT + m];
        float p1 = slog[1 * NTPAT + m];
        float p2 = slog[2 * NTPAT + m];
        float p3 = slog[3 * NTPAT + m];
        a[0][0] += p0 * x4.x; a[0][1] += p0 * x4.y; a[0][2] += p0 * x4.z; a[0][3] += p0 * x4.w;
        a[1][0] += p1 * x4.x; a[1][1] += p1 * x4.y; a[1][2] += p1 * x4.z; a[1][3] += p1 * x4.w;
        a[2][0] += p2 * x4.x; a[2][1] += p2 * x4.y; a[2][2] += p2 * x4.z; a[2][3] += p2 * x4.w;
        a[3][0] += p3 * x4.x; a[3][1] += p3 * x4.y; a[3][2] += p3 * x4.z; a[3][3] += p3 * x4.w;
    }
    // reduce across warps: two rounds through stp (16 warps x 512 slots)
    #pragma unroll
    for (int hh = 0; hh < 2; hh++) {
        #pragma unroll
        for (int j = 0; j < 4; j++) {
            stp[warp * 512 + hh * 128 + lane * 4 + j] = a[hh][j];
            stp[warp * 512 + (hh + 2) * 128 + 256 + lane * 4 + j - 256] = a[hh + 2][j];
        }
    }
    __syncthreads();
    if (tid < 512) {
        int hh = tid >> 7, c = tid & 127;
        float t = 0.0f;
        #pragma unroll
        for (int w2 = 0; w2 < 16; w2++) t += stp[w2 * 512 + hh * 128 + c];
        st[hh * 128 + c] = t * invsum[hh];
    }
    __syncthreads();

    // out[h][d] = b_v + sum_c t_h[c] * W_v[c][h*32+d]  (128 threads)
    if (tid < 128) {
        int hh = tid >> 5, d = tid & 31;
        float o = bkv[128 + hh * HD + d];
        const float* wv = Wkv + 128 + hh * HD + d;
        const float* th = st + hh * 128;
        #pragma unroll 4
        for (int c = 0; c < CDIM; c++)
            o += th[c] * wv[(size_t)c * 256];
        out[(size_t)b * CDIM + hh * HD + d] = o;
    }
}

// ---------------- launch ----------------
extern "C" void kernel_launch(void* const* d_in, const int* in_sizes, int n_in,
                              void* d_out, int out_size)
{
    const float* x      = (const float*)d_in[0];
    const float* xtotal = (const float*)d_in[1];
    const float* xavg   = (const float*)d_in[2];
    const float* mask   = (const float*)d_in[3];
    const float* Wq     = (const float*)d_in[4];
    const float* bq     = (const float*)d_in[5];
    const float* Wkv    = (const float*)d_in[6];
    const float* bkv    = (const float*)d_in[7];
    const float* btab   = (const float*)d_in[8];
    const int*   ridx   = (const int*)d_in[9];

    float* out     = (float*)d_out;
    float* out_avg = out + (size_t)200704u * 128u;

    static cudaStream_t s2 = nullptr;
    static cudaEvent_t evF = nullptr, evJ = nullptr;
    if (s2 == nullptr) {
        cudaStreamCreateWithFlags(&s2, cudaStreamNonBlocking);
        cudaEventCreateWithFlags(&evF, cudaEventDisableTiming);
        cudaEventCreateWithFlags(&evJ, cudaEventDisableTiming);
        cudaFuncSetAttribute(bf16_gemm<0, 0>, cudaFuncAttributeMaxDynamicSharedMemorySize, GEMM_SMEM);
        cudaFuncSetAttribute(bf16_gemm<1, 1>, cudaFuncAttributeMaxDynamicSharedMemorySize, GEMM_SMEM);
        cudaFuncSetAttribute(win_attn_mma, cudaFuncAttributeMaxDynamicSharedMemorySize, WIN_SMEM);
        cudaFuncSetAttribute(glob_attn3, cudaFuncAttributeMaxDynamicSharedMemorySize, GA_SMEM);
    }

    // fork: global path (GEMM-free, 1 block per image) on s2
    cudaEventRecord(evF, 0);
    cudaStreamWaitEvent(s2, evF, 0);
    glob_attn3<<<BIMG, 512, GA_SMEM, s2>>>(xtotal, xavg, Wq, bq, Wkv, bkv, out_avg);
    cudaEventRecord(evJ, s2);

    // window path on the default stream
    bias_build_kernel<<<(HEADS * NGT * NTOK + 255) / 256, 256>>>(btab, ridx);
    bf16_gemm<0, 0><<<dim3(1, 1568), 256, GEMM_SMEM>>>(x, nullptr, Wq, bq, 128, WQ_SCALE);
    bf16_gemm<1, 1><<<dim3(2, 1600), 256, GEMM_SMEM>>>(x, xavg, Wkv, bkv, 256, 1.0f);
    win_attn_mma<<<NWIN, 512, WIN_SMEM>>>(mask, out);

    // join
    cudaStreamWaitEvent(0, evJ, 0);
}

// round 13
// speedup vs baseline: 1.6191x; 1.3408x over previous
#include <cuda_runtime.h>
#include <cuda_bf16.h>
#include <cuda_fp16.h>

// ---------------- problem dims ----------------
#define NWIN   4096
#define NGT    49
#define NTOK   50
#define CDIM   128
#define HEADS  4
#define HD     32
#define BIMG   64
#define NTPAT  3136
#define WQ_SCALE 0.17677669529663687f   // 32^-0.5

// ---------------- device scratch ----------------
__device__ __half g_Qh [200704u * 128u];
__device__ __half g_Kwh[204800u * 128u];
__device__ __half g_Vwh[204800u * 128u];
__device__ __half g_Vwl[204800u * 128u];
__device__ float  g_bias[HEADS * NGT * NTOK];

// ---------------- helpers ----------------
__device__ __forceinline__ void mma_f16(float* c, const unsigned* a,
                                        unsigned b0, unsigned b1)
{
    asm volatile("mma.sync.aligned.m16n8k16.row.col.f32.f16.f16.f32 "
                 "{%0,%1,%2,%3}, {%4,%5,%6,%7}, {%8,%9}, {%0,%1,%2,%3};"
                 : "+f"(c[0]), "+f"(c[1]), "+f"(c[2]), "+f"(c[3])
                 : "r"(a[0]), "r"(a[1]), "r"(a[2]), "r"(a[3]), "r"(b0), "r"(b1));
}
__device__ __forceinline__ void ldsm_x4(unsigned* r, unsigned addr) {
    asm volatile("ldmatrix.sync.aligned.m8n8.x4.shared.b16 {%0,%1,%2,%3}, [%4];"
                 : "=r"(r[0]), "=r"(r[1]), "=r"(r[2]), "=r"(r[3]) : "r"(addr));
}
__device__ __forceinline__ void ldsm_x4_t(unsigned* r, unsigned addr) {
    asm volatile("ldmatrix.sync.aligned.m8n8.x4.trans.shared.b16 {%0,%1,%2,%3}, [%4];"
                 : "=r"(r[0]), "=r"(r[1]), "=r"(r[2]), "=r"(r[3]) : "r"(addr));
}
__device__ __forceinline__ unsigned s2u(const void* p) {
    return (unsigned)__cvta_generic_to_shared(p);
}
__device__ __forceinline__ unsigned h2pk(float a, float b) {
    __half2 t = __floats2half2_rn(a, b);
    return *reinterpret_cast<unsigned*>(&t);
}

// =====================================================================
// Unified 2-term split-fp16 projection GEMM, ONE launch for Q/K/V.
// bx=0: Q = (xc @ Wq + bq)*scale -> g_Qh (49-row layout, xavg rows skipped)
// bx=1: K = xc @ Wkv[:, :128] + bkv[:128]    -> g_Kwh
// bx=2: V = xc @ Wkv[:, 128:] + bkv[128:]    -> g_Vwh + g_Vwl
// A = gathered window-concat rows (M = 204800). A single fp16; B hi/lo fp16.
// =====================================================================
#define SBB_STR 136
#define SAB_STR 40
#define SBB_PL  (128 * SBB_STR)          // 17408 halves per B plane
#define SAB_PL  (128 * SAB_STR)          // 5120 halves per A buffer
#define GEMM_SMEM ((2 * SBB_PL + 2 * SAB_PL) * 2)   // 90112 bytes

__global__ void __launch_bounds__(256, 2)
qkv_gemm(const float* __restrict__ A, const float* __restrict__ Aavg,
         const float* __restrict__ Wq, const float* __restrict__ Wkv,
         const float* __restrict__ bq, const float* __restrict__ bkv)
{
    extern __shared__ __half sm[];
    __half* sBh = sm;
    __half* sBl = sm + SBB_PL;
    __half* sA  = sm + 2 * SBB_PL;       // [buf][128][40]

    const int tid  = threadIdx.x;
    const int lane = tid & 31;
    const int warp = tid >> 5;
    const int wm   = warp >> 2;
    const int wn   = warp & 3;
    const int g4   = lane >> 2;
    const int t4   = lane & 3;
    const int bx   = blockIdx.x;         // 0=Q, 1=K, 2=V
    const int by   = blockIdx.y;

    const int lr    = lane & 7;
    const int lt8   = ((lane >> 3) & 1) * 8;
    const int lk8   = (lane >> 4) * 8;
    const int bnoff = ((lane >> 4) & 1) * 8;
    const int bk8   = ((lane >> 3) & 1) * 8;

    // ---- gathered A row pointer ----
    const int a_row  = tid >> 1;
    const int a_half = (tid & 1) * 16;
    const int m = by * 128 + a_row;
    const float* arow;
    {
        int w  = m / NTOK;
        int rr = m - w * NTOK;
        arow = (rr < NGT) ? (A    + (size_t)(w * NGT + rr) * CDIM)
                          : (Aavg + (size_t)(w >> 6)       * CDIM);
    }

    // ---- B panel: coalesced column read, [n][k] hi/lo fp16 ----
    {
        const float* Wsel = (bx == 0) ? Wq : Wkv;
        const int Nsel    = (bx == 0) ? 128 : 256;
        const int coff    = (bx == 0) ? 0 : (bx - 1) * 128;
        const int nloc  = (warp & 3) * 32 + lane;
        const int kbase = (warp >> 2) * 64;
        const float* wp = Wsel + coff + nloc;
        #pragma unroll
        for (int kg = 0; kg < 16; kg++) {
            const int k = kbase + kg * 4;
            float v0 = wp[(size_t)(k + 0) * Nsel];
            float v1 = wp[(size_t)(k + 1) * Nsel];
            float v2 = wp[(size_t)(k + 2) * Nsel];
            float v3 = wp[(size_t)(k + 3) * Nsel];
            __half hh0 = __float2half_rn(v0);
            __half hh1 = __float2half_rn(v1);
            __half hh2 = __float2half_rn(v2);
            __half hh3 = __float2half_rn(v3);
            *(uint2*)(sBh + nloc * SBB_STR + k) = make_uint2(
                h2pk(v0, v1), h2pk(v2, v3));
            *(uint2*)(sBl + nloc * SBB_STR + k) = make_uint2(
                h2pk(v0 - __half2float(hh0), v1 - __half2float(hh1)),
                h2pk(v2 - __half2float(hh2), v3 - __half2float(hh3)));
        }
    }

    // ---- A prologue (single fp16 plane) ----
    float4 areg[4];
    #pragma unroll
    for (int j = 0; j < 4; j++)
        areg[j] = *(const float4*)(arow + a_half + 4 * j);
    {
        __half* dh = sA + a_row * SAB_STR + a_half;
        #pragma unroll
        for (int j = 0; j < 4; j++)
            *(uint2*)(dh + 4 * j) = make_uint2(h2pk(areg[j].x, areg[j].y),
                                               h2pk(areg[j].z, areg[j].w));
    }
    __syncthreads();

    float acc[4][4][4];
    #pragma unroll
    for (int mf = 0; mf < 4; mf++)
        #pragma unroll
        for (int nf = 0; nf < 4; nf++)
            #pragma unroll
            for (int c = 0; c < 4; c++) acc[mf][nf][c] = 0.0f;

    const int a_m0 = wm * 64;
    const int b_n0 = wn * 32;

    for (int kt = 0; kt < 4; kt++) {
        if (kt < 3) {
            #pragma unroll
            for (int j = 0; j < 4; j++)
                areg[j] = *(const float4*)(arow + (kt + 1) * 32 + a_half + 4 * j);
        }
        const __half* Ahp = sA + (kt & 1) * SAB_PL;

        #pragma unroll
        for (int st = 0; st < 2; st++) {
            const int kloc  = st * 16;
            const int kglob = kt * 32 + kloc;
            unsigned a[4][4];
            #pragma unroll
            for (int mf = 0; mf < 4; mf++) {
                const __half* pa_ = Ahp + (a_m0 + 16 * mf + lt8 + lr) * SAB_STR + kloc + lk8;
                ldsm_x4(a[mf], s2u(pa_));
            }
            unsigned bh[4][2], bl[4][2];
            #pragma unroll
            for (int p = 0; p < 2; p++) {
                const __half* pb = sBh + (b_n0 + 16 * p + bnoff + lr) * SBB_STR + kglob + bk8;
                unsigned t[4];
                ldsm_x4(t, s2u(pb));
                bh[2*p][0] = t[0]; bh[2*p][1] = t[1];
                bh[2*p+1][0] = t[2]; bh[2*p+1][1] = t[3];
                ldsm_x4(t, s2u(pb + SBB_PL));
                bl[2*p][0] = t[0]; bl[2*p][1] = t[1];
                bl[2*p+1][0] = t[2]; bl[2*p+1][1] = t[3];
            }
            // term-sliced: lo sweep then hi sweep (small-first per accumulator)
            #pragma unroll
            for (int nf = 0; nf < 4; nf++)
                #pragma unroll
                for (int mf = 0; mf < 4; mf++)
                    mma_f16(acc[mf][nf], a[mf], bl[nf][0], bl[nf][1]);
            #pragma unroll
            for (int nf = 0; nf < 4; nf++)
                #pragma unroll
                for (int mf = 0; mf < 4; mf++)
                    mma_f16(acc[mf][nf], a[mf], bh[nf][0], bh[nf][1]);
        }

        if (kt < 3) {
            __half* dh = sA + ((kt + 1) & 1) * SAB_PL + a_row * SAB_STR + a_half;
            #pragma unroll
            for (int j = 0; j < 4; j++)
                *(uint2*)(dh + 4 * j) = make_uint2(h2pk(areg[j].x, areg[j].y),
                                                   h2pk(areg[j].z, areg[j].w));
            __syncthreads();
        }
    }

    // ---- epilogue ----
    const float* bbase = (bx == 0) ? bq : ((bx == 1) ? bkv : bkv + 128);
    const float alpha  = (bx == 0) ? WQ_SCALE : 1.0f;

    #pragma unroll
    for (int mf = 0; mf < 4; mf++) {
        const int r0 = by * 128 + a_m0 + mf * 16 + g4;
        const int r1 = r0 + 8;
        const int w0 = r0 / NTOK, rr0 = r0 - w0 * NTOK;
        const int w1 = r1 / NTOK, rr1 = r1 - w1 * NTOK;
        #pragma unroll
        for (int nf = 0; nf < 4; nf++) {
            const int ncol = b_n0 + nf * 8 + 2 * t4;
            float bb0 = bbase[ncol];
            float bb1 = bbase[ncol + 1];
            float v00 = (acc[mf][nf][0] + bb0) * alpha;
            float v01 = (acc[mf][nf][1] + bb1) * alpha;
            float v10 = (acc[mf][nf][2] + bb0) * alpha;
            float v11 = (acc[mf][nf][3] + bb1) * alpha;
            if (bx == 0) {
                if (rr0 < NGT)
                    *(unsigned*)(g_Qh + (size_t)(w0 * NGT + rr0) * 128 + ncol) = h2pk(v00, v01);
                if (rr1 < NGT)
                    *(unsigned*)(g_Qh + (size_t)(w1 * NGT + rr1) * 128 + ncol) = h2pk(v10, v11);
            } else if (bx == 1) {
                *(unsigned*)(g_Kwh + (size_t)r0 * 128 + ncol) = h2pk(v00, v01);
                *(unsigned*)(g_Kwh + (size_t)r1 * 128 + ncol) = h2pk(v10, v11);
            } else {
                __half h00 = __float2half_rn(v00), h01 = __float2half_rn(v01);
                __half h10 = __float2half_rn(v10), h11 = __float2half_rn(v11);
                __half2 p0(h00, h01), p1(h10, h11);
                *(unsigned*)(g_Vwh + (size_t)r0 * 128 + ncol) = *(unsigned*)&p0;
                *(unsigned*)(g_Vwh + (size_t)r1 * 128 + ncol) = *(unsigned*)&p1;
                *(unsigned*)(g_Vwl + (size_t)r0 * 128 + ncol) =
                    h2pk(v00 - __half2float(h00), v01 - __half2float(h01));
                *(unsigned*)(g_Vwl + (size_t)r1 * 128 + ncol) =
                    h2pk(v10 - __half2float(h10), v11 - __half2float(h11));
            }
        }
    }
}

// ---------------- bias gather ----------------
__global__ void bias_build_kernel(const float* __restrict__ table,
                                  const int* __restrict__ ridx)
{
    int idx = blockIdx.x * 256 + threadIdx.x;
    if (idx < HEADS * NGT * NTOK) {
        int h  = idx / (NGT * NTOK);
        int ij = idx - h * (NGT * NTOK);
        g_bias[idx] = table[ridx[ij] * HEADS + h];
    }
}

// =====================================================================
// Window attention: 512 threads, 16 warps = (head, row-quarter).
// =====================================================================
#define WH_STR 136
#define WPLANE (64 * WH_STR)
#define WIN_SMEM (4 * WPLANE * 2)        // 69632 bytes

__global__ void __launch_bounds__(512)
win_attn_mma(const float* __restrict__ mask, float* __restrict__ out)
{
    extern __shared__ __half smh[];
    __half* sQ  = smh;
    __half* sK  = smh + WPLANE;
    __half* sVh = smh + 2 * WPLANE;
    __half* sVl = smh + 3 * WPLANE;

    const int w    = blockIdx.x;
    const int tid  = threadIdx.x;
    const int wid  = tid >> 5;
    const int h    = wid & 3;
    const int qtr  = wid >> 2;
    const int lane = tid & 31;
    const int g4   = lane >> 2;
    const int t4   = lane & 3;

    {
        uint4 z = make_uint4(0, 0, 0, 0);
        uint4* zq = (uint4*)(sQ + 49 * WH_STR);
        uint4* zk = (uint4*)(sK + 50 * WH_STR);
        uint4* zh = (uint4*)(sVh + 50 * WH_STR);
        uint4* zl = (uint4*)(sVl + 50 * WH_STR);
        for (int i = tid; i < 255; i += 512) zq[i] = z;
        for (int i = tid; i < 238; i += 512) { zk[i] = z; zh[i] = z; zl[i] = z; }
    }

    for (int idx = tid; idx < 49 * 16; idx += 512) {
        int r = idx >> 4, c = idx & 15;
        ((uint4*)(sQ + r * WH_STR))[c] =
            ((const uint4*)(g_Qh + (size_t)(w * NGT + r) * CDIM))[c];
    }
    for (int idx = tid; idx < 50 * 16; idx += 512) {
        int r = idx >> 4, c = idx & 15;
        size_t base = (size_t)(w * NTOK + r) * CDIM;
        ((uint4*)(sK  + r * WH_STR))[c] = ((const uint4*)(g_Kwh + base))[c];
        ((uint4*)(sVh + r * WH_STR))[c] = ((const uint4*)(g_Vwh + base))[c];
        ((uint4*)(sVl + r * WH_STR))[c] = ((const uint4*)(g_Vwl + base))[c];
    }
    __syncthreads();

    // ---- S = Q K^T ----
    float sacc[7][4];
    #pragma unroll
    for (int nf = 0; nf < 7; nf++)
        #pragma unroll
        for (int c = 0; c < 4; c++) sacc[nf][c] = 0.0f;

    #pragma unroll
    for (int ks = 0; ks < 2; ks++) {
        const int kc = h * HD + ks * 16 + 2 * t4;
        unsigned a[4];
        const __half* ap = sQ + (16 * qtr + g4) * WH_STR + kc;
        a[0] = *(const unsigned*)(ap);
        a[1] = *(const unsigned*)(ap + 8 * WH_STR);
        a[2] = *(const unsigned*)(ap + 8);
        a[3] = *(const unsigned*)(ap + 8 * WH_STR + 8);
        #pragma unroll
        for (int nf = 0; nf < 7; nf++) {
            const __half* bp = sK + (8 * nf + g4) * WH_STR + kc;
            unsigned b0 = *(const unsigned*)(bp);
            unsigned b1 = *(const unsigned*)(bp + 8);
            mma_f16(sacc[nf], a, b0, b1);
        }
    }

    // ---- bias + mask + softmax ----
    const float* bptr = g_bias + h * (NGT * NTOK);
    const float* mptr = mask + (size_t)(w & 63) * (NGT * NTOK);
    const int i0 = 16 * qtr + g4;
    const int i1 = i0 + 8;
    float m0 = -1e30f, m1 = -1e30f;
    #pragma unroll
    for (int nf = 0; nf < 7; nf++) {
        const int j0 = 8 * nf + 2 * t4;
        const int j1 = j0 + 1;
        float s0 = (i0 < NGT && j0 < NTOK) ? sacc[nf][0] + bptr[i0 * 50 + j0] + mptr[i0 * 50 + j0] : -1e30f;
        float s1 = (i0 < NGT && j1 < NTOK) ? sacc[nf][1] + bptr[i0 * 50 + j1] + mptr[i0 * 50 + j1] : -1e30f;
        float s2 = (i1 < NGT && j0 < NTOK) ? sacc[nf][2] + bptr[i1 * 50 + j0] + mptr[i1 * 50 + j0] : -1e30f;
        float s3 = (i1 < NGT && j1 < NTOK) ? sacc[nf][3] + bptr[i1 * 50 + j1] + mptr[i1 * 50 + j1] : -1e30f;
        sacc[nf][0] = s0; sacc[nf][1] = s1;
        sacc[nf][2] = s2; sacc[nf][3] = s3;
        m0 = fmaxf(m0, fmaxf(s0, s1));
        m1 = fmaxf(m1, fmaxf(s2, s3));
    }
    m0 = fmaxf(m0, __shfl_xor_sync(0xffffffffu, m0, 1));
    m0 = fmaxf(m0, __shfl_xor_sync(0xffffffffu, m0, 2));
    m1 = fmaxf(m1, __shfl_xor_sync(0xffffffffu, m1, 1));
    m1 = fmaxf(m1, __shfl_xor_sync(0xffffffffu, m1, 2));
    float r0 = 0.0f, r1 = 0.0f;
    #pragma unroll
    for (int nf = 0; nf < 7; nf++) {
        float p0 = __expf(sacc[nf][0] - m0);
        float p1 = __expf(sacc[nf][1] - m0);
        float p2 = __expf(sacc[nf][2] - m1);
        float p3 = __expf(sacc[nf][3] - m1);
        sacc[nf][0] = p0; sacc[nf][1] = p1;
        sacc[nf][2] = p2; sacc[nf][3] = p3;
        r0 += p0 + p1;
        r1 += p2 + p3;
    }
    r0 += __shfl_xor_sync(0xffffffffu, r0, 1);
    r0 += __shfl_xor_sync(0xffffffffu, r0, 2);
    r1 += __shfl_xor_sync(0xffffffffu, r1, 1);
    r1 += __shfl_xor_sync(0xffffffffu, r1, 2);

    // ---- pack P into fp16 A-fragments ----
    unsigned pa[4][4];
    #pragma unroll
    for (int ks = 0; ks < 3; ks++) {
        pa[ks][0] = h2pk(sacc[2*ks][0],   sacc[2*ks][1]);
        pa[ks][1] = h2pk(sacc[2*ks][2],   sacc[2*ks][3]);
        pa[ks][2] = h2pk(sacc[2*ks+1][0], sacc[2*ks+1][1]);
        pa[ks][3] = h2pk(sacc[2*ks+1][2], sacc[2*ks+1][3]);
    }
    pa[3][0] = h2pk(sacc[6][0], sacc[6][1]);
    pa[3][1] = h2pk(sacc[6][2], sacc[6][3]);
    pa[3][2] = 0u;
    pa[3][3] = 0u;

    // ---- O = P V ----
    float oacc[4][4];
    #pragma unroll
    for (int nf = 0; nf < 4; nf++)
        #pragma unroll
        for (int c = 0; c < 4; c++) oacc[nf][c] = 0.0f;

    const int lr    = lane & 7;
    const int vbk   = ((lane >> 3) & 1) * 8;
    const int vnoff = ((lane >> 4) & 1) * 8;

    #pragma unroll
    for (int ks = 0; ks < 4; ks++) {
        unsigned bh[4][2], bl[4][2];
        #pragma unroll
        for (int p = 0; p < 2; p++) {
            const __half* vp = sVh + (ks * 16 + vbk + lr) * WH_STR + h * HD + 16 * p + vnoff;
            unsigned t[4];
            ldsm_x4_t(t, s2u(vp));
            bh[2*p][0] = t[0]; bh[2*p][1] = t[1];
            bh[2*p+1][0] = t[2]; bh[2*p+1][1] = t[3];
            ldsm_x4_t(t, s2u(vp + WPLANE));
            bl[2*p][0] = t[0]; bl[2*p][1] = t[1];
            bl[2*p+1][0] = t[2]; bl[2*p+1][1] = t[3];
        }
        #pragma unroll
        for (int nf = 0; nf < 4; nf++)
            mma_f16(oacc[nf], pa[ks], bh[nf][0], bh[nf][1]);
        #pragma unroll
        for (int nf = 0; nf < 4; nf++)
            mma_f16(oacc[nf], pa[ks], bl[nf][0], bl[nf][1]);
    }

    // ---- normalize + store ----
    const float inv0 = 1.0f / r0;
    const float inv1 = 1.0f / r1;
    #pragma unroll
    for (int nf = 0; nf < 4; nf++) {
        const int col = h * HD + 8 * nf + 2 * t4;
        if (i0 < NGT) {
            float2 v; v.x = oacc[nf][0] * inv0; v.y = oacc[nf][1] * inv0;
            *(float2*)(out + (size_t)(w * NGT + i0) * CDIM + col) = v;
        }
        if (i1 < NGT) {
            float2 v; v.x = oacc[nf][2] * inv1; v.y = oacc[nf][3] * inv1;
            *(float2*)(out + (size_t)(w * NGT + i1) * CDIM + col) = v;
        }
    }
}

// =====================================================================
// Global-token attention, GEMM-free, all 4 heads per image-block.
// =====================================================================
#define GA_SQ    0
#define GA_SU    128
#define GA_SC0   (GA_SU + 512)
#define GA_SLOG  (GA_SC0 + 4)
#define GA_RED   (GA_SLOG + 4 * NTPAT)
#define GA_STP   (GA_RED + 512)
#define GA_ST    (GA_STP + 16 * 512)
#define GA_SMEM  ((GA_ST + 512) * 4)

__global__ void __launch_bounds__(512)
glob_attn3(const float* __restrict__ xtotal, const float* __restrict__ xavg,
           const float* __restrict__ Wq, const float* __restrict__ bq,
           const float* __restrict__ Wkv, const float* __restrict__ bkv,
           float* __restrict__ out)
{
    extern __shared__ float gs[];
    float* sq   = gs + GA_SQ;
    float* su   = gs + GA_SU;
    float* sc0  = gs + GA_SC0;
    float* slog = gs + GA_SLOG;
    float* red  = gs + GA_RED;
    float* stp  = gs + GA_STP;
    float* st   = gs + GA_ST;

    const int b = blockIdx.x;
    const int tid  = threadIdx.x;
    const int warp = tid >> 5;
    const int lane = tid & 31;

    if (tid < 128) {
        float acc = bq[tid];
        const float* xr = xavg + (size_t)b * CDIM;
        #pragma unroll 4
        for (int c = 0; c < CDIM; c++)
            acc += xr[c] * Wq[c * CDIM + tid];
        sq[tid] = acc;
    }
    __syncthreads();

    {
        const int hh = tid >> 7;
        const int c  = tid & 127;
        float acc = 0.0f;
        const float* wr = Wkv + (size_t)c * 256 + hh * HD;
        const float* qh = sq + hh * HD;
        #pragma unroll 8
        for (int j = 0; j < HD; j++)
            acc += wr[j] * qh[j];
        su[hh * 128 + c] = acc;
    }
    if (warp < 4) {
        float t = bkv[warp * HD + lane] * sq[warp * HD + lane];
        #pragma unroll
        for (int o = 16; o; o >>= 1) t += __shfl_down_sync(0xffffffffu, t, o);
        if (lane == 0) sc0[warp] = t;
    }
    __syncthreads();

    const float* Xb = xtotal + (size_t)b * NTPAT * CDIM;
    float u[4][4];
    #pragma unroll
    for (int hh = 0; hh < 4; hh++) {
        u[hh][0] = su[hh * 128 + lane * 4 + 0];
        u[hh][1] = su[hh * 128 + lane * 4 + 1];
        u[hh][2] = su[hh * 128 + lane * 4 + 2];
        u[hh][3] = su[hh * 128 + lane * 4 + 3];
    }
    for (int m = warp; m < NTPAT; m += 16) {
        float4 x4 = *(const float4*)(Xb + (size_t)m * CDIM + lane * 4);
        float p0 = x4.x * u[0][0] + x4.y * u[0][1] + x4.z * u[0][2] + x4.w * u[0][3];
        float p1 = x4.x * u[1][0] + x4.y * u[1][1] + x4.z * u[1][2] + x4.w * u[1][3];
        float p2 = x4.x * u[2][0] + x4.y * u[2][1] + x4.z * u[2][2] + x4.w * u[2][3];
        float p3 = x4.x * u[3][0] + x4.y * u[3][1] + x4.z * u[3][2] + x4.w * u[3][3];
        #pragma unroll
        for (int o = 16; o; o >>= 1) {
            p0 += __shfl_down_sync(0xffffffffu, p0, o);
            p1 += __shfl_down_sync(0xffffffffu, p1, o);
            p2 += __shfl_down_sync(0xffffffffu, p2, o);
            p3 += __shfl_down_sync(0xffffffffu, p3, o);
        }
        if (lane == 0) {
            slog[0 * NTPAT + m] = p0 + sc0[0];
            slog[1 * NTPAT + m] = p1 + sc0[1];
            slog[2 * NTPAT + m] = p2 + sc0[2];
            slog[3 * NTPAT + m] = p3 + sc0[3];
        }
    }
    __syncthreads();

    float invsum[4];
    #pragma unroll
    for (int hh = 0; hh < 4; hh++) {
        float* lg = slog + hh * NTPAT;
        float mx = -1e30f;
        for (int m = tid; m < NTPAT; m += 512) mx = fmaxf(mx, lg[m]);
        red[tid] = mx; __syncthreads();
        for (int s = 256; s; s >>= 1) { if (tid < s) red[tid] = fmaxf(red[tid], red[tid + s]); __syncthreads(); }
        mx = red[0]; __syncthreads();
        float sum = 0.0f;
        for (int m = tid; m < NTPAT; m += 512) {
            float e = expf(lg[m] - mx);
            lg[m] = e;
            sum += e;
        }
        red[tid] = sum; __syncthreads();
        for (int s = 256; s; s >>= 1) { if (tid < s) red[tid] += red[tid + s]; __syncthreads(); }
        invsum[hh] = 1.0f / red[0];
        __syncthreads();
    }

    float a[4][4];
    #pragma unroll
    for (int hh = 0; hh < 4; hh++)
        #pragma unroll
        for (int j = 0; j < 4; j++) a[hh][j] = 0.0f;
    for (int m = warp; m < NTPAT; m += 16) {
        float4 x4 = *(const float4*)(Xb + (size_t)m * CDIM + lane * 4);
        float p0 = slog[0 * NTPAT + m];
        float p1 = slog[1 * NTPAT + m];
        float p2 = slog[2 * NTPAT + m];
        float p3 = slog[3 * NTPAT + m];
        a[0][0] += p0 * x4.x; a[0][1] += p0 * x4.y; a[0][2] += p0 * x4.z; a[0][3] += p0 * x4.w;
        a[1][0] += p1 * x4.x; a[1][1] += p1 * x4.y; a[1][2] += p1 * x4.z; a[1][3] += p1 * x4.w;
        a[2][0] += p2 * x4.x; a[2][1] += p2 * x4.y; a[2][2] += p2 * x4.z; a[2][3] += p2 * x4.w;
        a[3][0] += p3 * x4.x; a[3][1] += p3 * x4.y; a[3][2] += p3 * x4.z; a[3][3] += p3 * x4.w;
    }
    #pragma unroll
    for (int hh = 0; hh < 4; hh++)
        #pragma unroll
        for (int j = 0; j < 4; j++)
            stp[warp * 512 + hh * 128 + lane * 4 + j] = a[hh][j];
    __syncthreads();
    {
        int hh = tid >> 7, c = tid & 127;
        float t = 0.0f;
        #pragma unroll
        for (int w2 = 0; w2 < 16; w2++) t += stp[w2 * 512 + hh * 128 + c];
        st[hh * 128 + c] = t * invsum[hh];
    }
    __syncthreads();

    if (tid < 128) {
        int hh = tid >> 5, d = tid & 31;
        float o = bkv[128 + hh * HD + d];
        const float* wv = Wkv + 128 + hh * HD + d;
        const float* th = st + hh * 128;
        #pragma unroll 4
        for (int c = 0; c < CDIM; c++)
            o += th[c] * wv[(size_t)c * 256];
        out[(size_t)b * CDIM + hh * HD + d] = o;
    }
}

// ---------------- launch ----------------
extern "C" void kernel_launch(void* const* d_in, const int* in_sizes, int n_in,
                              void* d_out, int out_size)
{
    const float* x      = (const float*)d_in[0];
    const float* xtotal = (const float*)d_in[1];
    const float* xavg   = (const float*)d_in[2];
    const float* mask   = (const float*)d_in[3];
    const float* Wq     = (const float*)d_in[4];
    const float* bq     = (const float*)d_in[5];
    const float* Wkv    = (const float*)d_in[6];
    const float* bkv    = (const float*)d_in[7];
    const float* btab   = (const float*)d_in[8];
    const int*   ridx   = (const int*)d_in[9];

    float* out     = (float*)d_out;
    float* out_avg = out + (size_t)200704u * 128u;

    static cudaStream_t s2 = nullptr;
    static cudaEvent_t evF = nullptr, evB = nullptr, evJ = nullptr;
    if (s2 == nullptr) {
        cudaStreamCreateWithFlags(&s2, cudaStreamNonBlocking);
        cudaEventCreateWithFlags(&evF, cudaEventDisableTiming);
        cudaEventCreateWithFlags(&evB, cudaEventDisableTiming);
        cudaEventCreateWithFlags(&evJ, cudaEventDisableTiming);
        cudaFuncSetAttribute(qkv_gemm, cudaFuncAttributeMaxDynamicSharedMemorySize, GEMM_SMEM);
        cudaFuncSetAttribute(win_attn_mma, cudaFuncAttributeMaxDynamicSharedMemorySize, WIN_SMEM);
        cudaFuncSetAttribute(glob_attn3, cudaFuncAttributeMaxDynamicSharedMemorySize, GA_SMEM);
    }

    // fork: bias gather + global path on s2
    cudaEventRecord(evF, 0);
    cudaStreamWaitEvent(s2, evF, 0);
    bias_build_kernel<<<(HEADS * NGT * NTOK + 255) / 256, 256, 0, s2>>>(btab, ridx);
    cudaEventRecord(evB, s2);
    glob_attn3<<<BIMG, 512, GA_SMEM, s2>>>(xtotal, xavg, Wq, bq, Wkv, bkv, out_avg);
    cudaEventRecord(evJ, s2);

    // window path: one unified QKV GEMM, then attention
    qkv_gemm<<<dim3(3, 1600), 256, GEMM_SMEM>>>(x, xavg, Wq, Wkv, bq, bkv);
    cudaStreamWaitEvent(0, evB, 0);       // g_bias ready
    win_attn_mma<<<NWIN, 512, WIN_SMEM>>>(mask, out);

    // join
    cudaStreamWaitEvent(0, evJ, 0);
}

// round 15
// speedup vs baseline: 1.7316x; 1.0695x over previous
#include <cuda_runtime.h>
#include <cuda_bf16.h>
#include <cuda_fp16.h>

// ---------------- problem dims ----------------
#define NWIN   4096
#define NGT    49
#define NTOK   50
#define CDIM   128
#define HEADS  4
#define HD     32
#define BIMG   64
#define NTPAT  3136
#define WQ_SCALE 0.17677669529663687f   // 32^-0.5

// ---------------- device scratch ----------------
__device__ __half g_Qh [200704u * 128u];
__device__ __half g_Kwh[204800u * 128u];
__device__ __half g_Vwh[204800u * 128u];
__device__ float  g_bias[HEADS * NGT * NTOK];

// ---------------- helpers ----------------
__device__ __forceinline__ void mma_f16(float* c, const unsigned* a,
                                        unsigned b0, unsigned b1)
{
    asm volatile("mma.sync.aligned.m16n8k16.row.col.f32.f16.f16.f32 "
                 "{%0,%1,%2,%3}, {%4,%5,%6,%7}, {%8,%9}, {%0,%1,%2,%3};"
                 : "+f"(c[0]), "+f"(c[1]), "+f"(c[2]), "+f"(c[3])
                 : "r"(a[0]), "r"(a[1]), "r"(a[2]), "r"(a[3]), "r"(b0), "r"(b1));
}
__device__ __forceinline__ void ldsm_x4(unsigned* r, unsigned addr) {
    asm volatile("ldmatrix.sync.aligned.m8n8.x4.shared.b16 {%0,%1,%2,%3}, [%4];"
                 : "=r"(r[0]), "=r"(r[1]), "=r"(r[2]), "=r"(r[3]) : "r"(addr));
}
__device__ __forceinline__ void ldsm_x4_t(unsigned* r, unsigned addr) {
    asm volatile("ldmatrix.sync.aligned.m8n8.x4.trans.shared.b16 {%0,%1,%2,%3}, [%4];"
                 : "=r"(r[0]), "=r"(r[1]), "=r"(r[2]), "=r"(r[3]) : "r"(addr));
}
__device__ __forceinline__ unsigned s2u(const void* p) {
    return (unsigned)__cvta_generic_to_shared(p);
}
__device__ __forceinline__ unsigned h2pk(float a, float b) {
    __half2 t = __floats2half2_rn(a, b);
    return *reinterpret_cast<unsigned*>(&t);
}
__device__ __forceinline__ void cpa16(unsigned dst, const void* src) {
    asm volatile("cp.async.ca.shared.global [%0], [%1], 16;" :: "r"(dst), "l"(src));
}
__device__ __forceinline__ void cpa_wait() {
    asm volatile("cp.async.commit_group;\n\tcp.async.wait_group 0;" ::: "memory");
}

// =====================================================================
// Unified 2-term split-fp16 projection GEMM, ONE launch for Q/K/V.
// bx=0: Q -> g_Qh (49-row layout); bx=1: K -> g_Kwh; bx=2: V -> g_Vwh.
// =====================================================================
#define SBB_STR 136
#define SAB_STR 40
#define SBB_PL  (128 * SBB_STR)
#define SAB_PL  (128 * SAB_STR)
#define GEMM_SMEM ((2 * SBB_PL + 2 * SAB_PL) * 2)   // 90112 bytes

__global__ void __launch_bounds__(256, 2)
qkv_gemm(const float* __restrict__ A, const float* __restrict__ Aavg,
         const float* __restrict__ Wq, const float* __restrict__ Wkv,
         const float* __restrict__ bq, const float* __restrict__ bkv)
{
    extern __shared__ __half sm[];
    __half* sBh = sm;
    __half* sBl = sm + SBB_PL;
    __half* sA  = sm + 2 * SBB_PL;

    const int tid  = threadIdx.x;
    const int lane = tid & 31;
    const int warp = tid >> 5;
    const int wm   = warp >> 2;
    const int wn   = warp & 3;
    const int g4   = lane >> 2;
    const int t4   = lane & 3;
    const int bx   = blockIdx.x;
    const int by   = blockIdx.y;

    const int lr    = lane & 7;
    const int lt8   = ((lane >> 3) & 1) * 8;
    const int lk8   = (lane >> 4) * 8;
    const int bnoff = ((lane >> 4) & 1) * 8;
    const int bk8   = ((lane >> 3) & 1) * 8;

    const int a_row  = tid >> 1;
    const int a_half = (tid & 1) * 16;
    const int m = by * 128 + a_row;
    const float* arow;
    {
        int w  = m / NTOK;
        int rr = m - w * NTOK;
        arow = (rr < NGT) ? (A    + (size_t)(w * NGT + rr) * CDIM)
                          : (Aavg + (size_t)(w >> 6)       * CDIM);
    }

    // ---- B panel ----
    {
        const float* Wsel = (bx == 0) ? Wq : Wkv;
        const int Nsel    = (bx == 0) ? 128 : 256;
        const int coff    = (bx == 0) ? 0 : (bx - 1) * 128;
        const int nloc  = (warp & 3) * 32 + lane;
        const int kbase = (warp >> 2) * 64;
        const float* wp = Wsel + coff + nloc;
        #pragma unroll
        for (int kg = 0; kg < 16; kg++) {
            const int k = kbase + kg * 4;
            float v0 = wp[(size_t)(k + 0) * Nsel];
            float v1 = wp[(size_t)(k + 1) * Nsel];
            float v2 = wp[(size_t)(k + 2) * Nsel];
            float v3 = wp[(size_t)(k + 3) * Nsel];
            __half hh0 = __float2half_rn(v0);
            __half hh1 = __float2half_rn(v1);
            __half hh2 = __float2half_rn(v2);
            __half hh3 = __float2half_rn(v3);
            *(uint2*)(sBh + nloc * SBB_STR + k) = make_uint2(
                h2pk(v0, v1), h2pk(v2, v3));
            *(uint2*)(sBl + nloc * SBB_STR + k) = make_uint2(
                h2pk(v0 - __half2float(hh0), v1 - __half2float(hh1)),
                h2pk(v2 - __half2float(hh2), v3 - __half2float(hh3)));
        }
    }

    // ---- A prologue ----
    float4 areg[4];
    #pragma unroll
    for (int j = 0; j < 4; j++)
        areg[j] = *(const float4*)(arow + a_half + 4 * j);
    {
        __half* dh = sA + a_row * SAB_STR + a_half;
        #pragma unroll
        for (int j = 0; j < 4; j++)
            *(uint2*)(dh + 4 * j) = make_uint2(h2pk(areg[j].x, areg[j].y),
                                               h2pk(areg[j].z, areg[j].w));
    }
    __syncthreads();

    float acc[4][4][4];
    #pragma unroll
    for (int mf = 0; mf < 4; mf++)
        #pragma unroll
        for (int nf = 0; nf < 4; nf++)
            #pragma unroll
            for (int c = 0; c < 4; c++) acc[mf][nf][c] = 0.0f;

    const int a_m0 = wm * 64;
    const int b_n0 = wn * 32;

    for (int kt = 0; kt < 4; kt++) {
        if (kt < 3) {
            #pragma unroll
            for (int j = 0; j < 4; j++)
                areg[j] = *(const float4*)(arow + (kt + 1) * 32 + a_half + 4 * j);
        }
        const __half* Ahp = sA + (kt & 1) * SAB_PL;

        #pragma unroll
        for (int st = 0; st < 2; st++) {
            const int kloc  = st * 16;
            const int kglob = kt * 32 + kloc;
            unsigned a[4][4];
            #pragma unroll
            for (int mf = 0; mf < 4; mf++) {
                const __half* pa_ = Ahp + (a_m0 + 16 * mf + lt8 + lr) * SAB_STR + kloc + lk8;
                ldsm_x4(a[mf], s2u(pa_));
            }
            unsigned bh[4][2], bl[4][2];
            #pragma unroll
            for (int p = 0; p < 2; p++) {
                const __half* pb = sBh + (b_n0 + 16 * p + bnoff + lr) * SBB_STR + kglob + bk8;
                unsigned t[4];
                ldsm_x4(t, s2u(pb));
                bh[2*p][0] = t[0]; bh[2*p][1] = t[1];
                bh[2*p+1][0] = t[2]; bh[2*p+1][1] = t[3];
                ldsm_x4(t, s2u(pb + SBB_PL));
                bl[2*p][0] = t[0]; bl[2*p][1] = t[1];
                bl[2*p+1][0] = t[2]; bl[2*p+1][1] = t[3];
            }
            #pragma unroll
            for (int nf = 0; nf < 4; nf++)
                #pragma unroll
                for (int mf = 0; mf < 4; mf++)
                    mma_f16(acc[mf][nf], a[mf], bl[nf][0], bl[nf][1]);
            #pragma unroll
            for (int nf = 0; nf < 4; nf++)
                #pragma unroll
                for (int mf = 0; mf < 4; mf++)
                    mma_f16(acc[mf][nf], a[mf], bh[nf][0], bh[nf][1]);
        }

        if (kt < 3) {
            __half* dh = sA + ((kt + 1) & 1) * SAB_PL + a_row * SAB_STR + a_half;
            #pragma unroll
            for (int j = 0; j < 4; j++)
                *(uint2*)(dh + 4 * j) = make_uint2(h2pk(areg[j].x, areg[j].y),
                                                   h2pk(areg[j].z, areg[j].w));
            __syncthreads();
        }
    }

    // ---- epilogue ----
    const float* bbase = (bx == 0) ? bq : ((bx == 1) ? bkv : bkv + 128);
    const float alpha  = (bx == 0) ? WQ_SCALE : 1.0f;

    #pragma unroll
    for (int mf = 0; mf < 4; mf++) {
        const int r0 = by * 128 + a_m0 + mf * 16 + g4;
        const int r1 = r0 + 8;
        const int w0 = r0 / NTOK, rr0 = r0 - w0 * NTOK;
        const int w1 = r1 / NTOK, rr1 = r1 - w1 * NTOK;
        #pragma unroll
        for (int nf = 0; nf < 4; nf++) {
            const int ncol = b_n0 + nf * 8 + 2 * t4;
            float bb0 = bbase[ncol];
            float bb1 = bbase[ncol + 1];
            float v00 = (acc[mf][nf][0] + bb0) * alpha;
            float v01 = (acc[mf][nf][1] + bb1) * alpha;
            float v10 = (acc[mf][nf][2] + bb0) * alpha;
            float v11 = (acc[mf][nf][3] + bb1) * alpha;
            if (bx == 0) {
                if (rr0 < NGT)
                    *(unsigned*)(g_Qh + (size_t)(w0 * NGT + rr0) * 128 + ncol) = h2pk(v00, v01);
                if (rr1 < NGT)
                    *(unsigned*)(g_Qh + (size_t)(w1 * NGT + rr1) * 128 + ncol) = h2pk(v10, v11);
            } else {
                __half* Cout = (bx == 1) ? g_Kwh : g_Vwh;
                *(unsigned*)(Cout + (size_t)r0 * 128 + ncol) = h2pk(v00, v01);
                *(unsigned*)(Cout + (size_t)r1 * 128 + ncol) = h2pk(v10, v11);
            }
        }
    }
}

// ---------------- bias gather ----------------
__global__ void bias_build_kernel(const float* __restrict__ table,
                                  const int* __restrict__ ridx)
{
    int idx = blockIdx.x * 256 + threadIdx.x;
    if (idx < HEADS * NGT * NTOK) {
        int h  = idx / (NGT * NTOK);
        int ij = idx - h * (NGT * NTOK);
        g_bias[idx] = table[ridx[ij] * HEADS + h];
    }
}

// =====================================================================
// Window attention: 512 threads, 16 warps = (head, row-quarter).
// 3 planes (Q, K, V single fp16), cp.async fills, 52.2 KB smem.
// =====================================================================
#define WH_STR 136
#define WPLANE (64 * WH_STR)
#define WIN_SMEM (3 * WPLANE * 2)        // 52224 bytes

__global__ void __launch_bounds__(512)
win_attn_mma(const float* __restrict__ mask, float* __restrict__ out)
{
    extern __shared__ __half smh[];
    __half* sQ  = smh;
    __half* sK  = smh + WPLANE;
    __half* sV  = smh + 2 * WPLANE;

    const int w    = blockIdx.x;
    const int tid  = threadIdx.x;
    const int wid  = tid >> 5;
    const int h    = wid & 3;
    const int qtr  = wid >> 2;
    const int lane = tid & 31;
    const int g4   = lane >> 2;
    const int t4   = lane & 3;

    // zero pad rows (full rows incl. pad cols)
    {
        uint4 z = make_uint4(0, 0, 0, 0);
        uint4* zq = (uint4*)(sQ + 49 * WH_STR);
        uint4* zk = (uint4*)(sK + 50 * WH_STR);
        uint4* zv = (uint4*)(sV + 50 * WH_STR);
        for (int i = tid; i < 255; i += 512) zq[i] = z;
        for (int i = tid; i < 238; i += 512) { zk[i] = z; zv[i] = z; }
    }

    // fills via cp.async (16B each)
    for (int idx = tid; idx < 49 * 16; idx += 512) {
        int r = idx >> 4, c = idx & 15;
        cpa16(s2u(sQ + r * WH_STR + c * 8),
              g_Qh + (size_t)(w * NGT + r) * CDIM + c * 8);
    }
    for (int idx = tid; idx < 50 * 16; idx += 512) {
        int r = idx >> 4, c = idx & 15;
        size_t base = (size_t)(w * NTOK + r) * CDIM + c * 8;
        cpa16(s2u(sK + r * WH_STR + c * 8), g_Kwh + base);
        cpa16(s2u(sV + r * WH_STR + c * 8), g_Vwh + base);
    }
    cpa_wait();
    __syncthreads();

    // ---- S = Q K^T ----
    float sacc[7][4];
    #pragma unroll
    for (int nf = 0; nf < 7; nf++)
        #pragma unroll
        for (int c = 0; c < 4; c++) sacc[nf][c] = 0.0f;

    #pragma unroll
    for (int ks = 0; ks < 2; ks++) {
        const int kc = h * HD + ks * 16 + 2 * t4;
        unsigned a[4];
        const __half* ap = sQ + (16 * qtr + g4) * WH_STR + kc;
        a[0] = *(const unsigned*)(ap);
        a[1] = *(const unsigned*)(ap + 8 * WH_STR);
        a[2] = *(const unsigned*)(ap + 8);
        a[3] = *(const unsigned*)(ap + 8 * WH_STR + 8);
        #pragma unroll
        for (int nf = 0; nf < 7; nf++) {
            const __half* bp = sK + (8 * nf + g4) * WH_STR + kc;
            unsigned b0 = *(const unsigned*)(bp);
            unsigned b1 = *(const unsigned*)(bp + 8);
            mma_f16(sacc[nf], a, b0, b1);
        }
    }

    // ---- bias + mask + softmax ----
    const float* bptr = g_bias + h * (NGT * NTOK);
    const float* mptr = mask + (size_t)(w & 63) * (NGT * NTOK);
    const int i0 = 16 * qtr + g4;
    const int i1 = i0 + 8;
    float m0 = -1e30f, m1 = -1e30f;
    #pragma unroll
    for (int nf = 0; nf < 7; nf++) {
        const int j0 = 8 * nf + 2 * t4;
        const int j1 = j0 + 1;
        float s0 = (i0 < NGT && j0 < NTOK) ? sacc[nf][0] + bptr[i0 * 50 + j0] + mptr[i0 * 50 + j0] : -1e30f;
        float s1 = (i0 < NGT && j1 < NTOK) ? sacc[nf][1] + bptr[i0 * 50 + j1] + mptr[i0 * 50 + j1] : -1e30f;
        float s2 = (i1 < NGT && j0 < NTOK) ? sacc[nf][2] + bptr[i1 * 50 + j0] + mptr[i1 * 50 + j0] : -1e30f;
        float s3 = (i1 < NGT && j1 < NTOK) ? sacc[nf][3] + bptr[i1 * 50 + j1] + mptr[i1 * 50 + j1] : -1e30f;
        sacc[nf][0] = s0; sacc[nf][1] = s1;
        sacc[nf][2] = s2; sacc[nf][3] = s3;
        m0 = fmaxf(m0, fmaxf(s0, s1));
        m1 = fmaxf(m1, fmaxf(s2, s3));
    }
    m0 = fmaxf(m0, __shfl_xor_sync(0xffffffffu, m0, 1));
    m0 = fmaxf(m0, __shfl_xor_sync(0xffffffffu, m0, 2));
    m1 = fmaxf(m1, __shfl_xor_sync(0xffffffffu, m1, 1));
    m1 = fmaxf(m1, __shfl_xor_sync(0xffffffffu, m1, 2));
    float r0 = 0.0f, r1 = 0.0f;
    #pragma unroll
    for (int nf = 0; nf < 7; nf++) {
        float p0 = __expf(sacc[nf][0] - m0);
        float p1 = __expf(sacc[nf][1] - m0);
        float p2 = __expf(sacc[nf][2] - m1);
        float p3 = __expf(sacc[nf][3] - m1);
        sacc[nf][0] = p0; sacc[nf][1] = p1;
        sacc[nf][2] = p2; sacc[nf][3] = p3;
        r0 += p0 + p1;
        r1 += p2 + p3;
    }
    r0 += __shfl_xor_sync(0xffffffffu, r0, 1);
    r0 += __shfl_xor_sync(0xffffffffu, r0, 2);
    r1 += __shfl_xor_sync(0xffffffffu, r1, 1);
    r1 += __shfl_xor_sync(0xffffffffu, r1, 2);

    // ---- pack P into fp16 A-fragments ----
    unsigned pa[4][4];
    #pragma unroll
    for (int ks = 0; ks < 3; ks++) {
        pa[ks][0] = h2pk(sacc[2*ks][0],   sacc[2*ks][1]);
        pa[ks][1] = h2pk(sacc[2*ks][2],   sacc[2*ks][3]);
        pa[ks][2] = h2pk(sacc[2*ks+1][0], sacc[2*ks+1][1]);
        pa[ks][3] = h2pk(sacc[2*ks+1][2], sacc[2*ks+1][3]);
    }
    pa[3][0] = h2pk(sacc[6][0], sacc[6][1]);
    pa[3][1] = h2pk(sacc[6][2], sacc[6][3]);
    pa[3][2] = 0u;
    pa[3][3] = 0u;

    // ---- O = P V (single-term fp16 V) ----
    float oacc[4][4];
    #pragma unroll
    for (int nf = 0; nf < 4; nf++)
        #pragma unroll
        for (int c = 0; c < 4; c++) oacc[nf][c] = 0.0f;

    const int lr    = lane & 7;
    const int vbk   = ((lane >> 3) & 1) * 8;
    const int vnoff = ((lane >> 4) & 1) * 8;

    #pragma unroll
    for (int ks = 0; ks < 4; ks++) {
        unsigned bh[4][2];
        #pragma unroll
        for (int p = 0; p < 2; p++) {
            const __half* vp = sV + (ks * 16 + vbk + lr) * WH_STR + h * HD + 16 * p + vnoff;
            unsigned t[4];
            ldsm_x4_t(t, s2u(vp));
            bh[2*p][0] = t[0]; bh[2*p][1] = t[1];
            bh[2*p+1][0] = t[2]; bh[2*p+1][1] = t[3];
        }
        #pragma unroll
        for (int nf = 0; nf < 4; nf++)
            mma_f16(oacc[nf], pa[ks], bh[nf][0], bh[nf][1]);
    }

    // ---- normalize + store ----
    const float inv0 = 1.0f / r0;
    const float inv1 = 1.0f / r1;
    #pragma unroll
    for (int nf = 0; nf < 4; nf++) {
        const int col = h * HD + 8 * nf + 2 * t4;
        if (i0 < NGT) {
            float2 v; v.x = oacc[nf][0] * inv0; v.y = oacc[nf][1] * inv0;
            *(float2*)(out + (size_t)(w * NGT + i0) * CDIM + col) = v;
        }
        if (i1 < NGT) {
            float2 v; v.x = oacc[nf][2] * inv1; v.y = oacc[nf][3] * inv1;
            *(float2*)(out + (size_t)(w * NGT + i1) * CDIM + col) = v;
        }
    }
}

// =====================================================================
// Global-token attention, GEMM-free, all 4 heads per image-block.
// =====================================================================
#define GA_SQ    0
#define GA_SU    128
#define GA_SC0   (GA_SU + 512)
#define GA_SLOG  (GA_SC0 + 4)
#define GA_RED   (GA_SLOG + 4 * NTPAT)
#define GA_STP   (GA_RED + 512)
#define GA_ST    (GA_STP + 16 * 512)
#define GA_SMEM  ((GA_ST + 512) * 4)

__global__ void __launch_bounds__(512)
glob_attn3(const float* __restrict__ xtotal, const float* __restrict__ xavg,
           const float* __restrict__ Wq, const float* __restrict__ bq,
           const float* __restrict__ Wkv, const float* __restrict__ bkv,
           float* __restrict__ out)
{
    extern __shared__ float gs[];
    float* sq   = gs + GA_SQ;
    float* su   = gs + GA_SU;
    float* sc0  = gs + GA_SC0;
    float* slog = gs + GA_SLOG;
    float* red  = gs + GA_RED;
    float* stp  = gs + GA_STP;
    float* st   = gs + GA_ST;

    const int b = blockIdx.x;
    const int tid  = threadIdx.x;
    const int warp = tid >> 5;
    const int lane = tid & 31;

    if (tid < 128) {
        float acc = bq[tid];
        const float* xr = xavg + (size_t)b * CDIM;
        #pragma unroll 4
        for (int c = 0; c < CDIM; c++)
            acc += xr[c] * Wq[c * CDIM + tid];
        sq[tid] = acc;
    }
    __syncthreads();

    {
        const int hh = tid >> 7;
        const int c  = tid & 127;
        float acc = 0.0f;
        const float* wr = Wkv + (size_t)c * 256 + hh * HD;
        const float* qh = sq + hh * HD;
        #pragma unroll 8
        for (int j = 0; j < HD; j++)
            acc += wr[j] * qh[j];
        su[hh * 128 + c] = acc;
    }
    if (warp < 4) {
        float t = bkv[warp * HD + lane] * sq[warp * HD + lane];
        #pragma unroll
        for (int o = 16; o; o >>= 1) t += __shfl_down_sync(0xffffffffu, t, o);
        if (lane == 0) sc0[warp] = t;
    }
    __syncthreads();

    const float* Xb = xtotal + (size_t)b * NTPAT * CDIM;
    float u[4][4];
    #pragma unroll
    for (int hh = 0; hh < 4; hh++) {
        u[hh][0] = su[hh * 128 + lane * 4 + 0];
        u[hh][1] = su[hh * 128 + lane * 4 + 1];
        u[hh][2] = su[hh * 128 + lane * 4 + 2];
        u[hh][3] = su[hh * 128 + lane * 4 + 3];
    }
    for (int m = warp; m < NTPAT; m += 16) {
        float4 x4 = *(const float4*)(Xb + (size_t)m * CDIM + lane * 4);
        float p0 = x4.x * u[0][0] + x4.y * u[0][1] + x4.z * u[0][2] + x4.w * u[0][3];
        float p1 = x4.x * u[1][0] + x4.y * u[1][1] + x4.z * u[1][2] + x4.w * u[1][3];
        float p2 = x4.x * u[2][0] + x4.y * u[2][1] + x4.z * u[2][2] + x4.w * u[2][3];
        float p3 = x4.x * u[3][0] + x4.y * u[3][1] + x4.z * u[3][2] + x4.w * u[3][3];
        #pragma unroll
        for (int o = 16; o; o >>= 1) {
            p0 += __shfl_down_sync(0xffffffffu, p0, o);
            p1 += __shfl_down_sync(0xffffffffu, p1, o);
            p2 += __shfl_down_sync(0xffffffffu, p2, o);
            p3 += __shfl_down_sync(0xffffffffu, p3, o);
        }
        if (lane == 0) {
            slog[0 * NTPAT + m] = p0 + sc0[0];
            slog[1 * NTPAT + m] = p1 + sc0[1];
            slog[2 * NTPAT + m] = p2 + sc0[2];
            slog[3 * NTPAT + m] = p3 + sc0[3];
        }
    }
    __syncthreads();

    float invsum[4];
    #pragma unroll
    for (int hh = 0; hh < 4; hh++) {
        float* lg = slog + hh * NTPAT;
        float mx = -1e30f;
        for (int m = tid; m < NTPAT; m += 512) mx = fmaxf(mx, lg[m]);
        red[tid] = mx; __syncthreads();
        for (int s = 256; s; s >>= 1) { if (tid < s) red[tid] = fmaxf(red[tid], red[tid + s]); __syncthreads(); }
        mx = red[0]; __syncthreads();
        float sum = 0.0f;
        for (int m = tid; m < NTPAT; m += 512) {
            float e = expf(lg[m] - mx);
            lg[m] = e;
            sum += e;
        }
        red[tid] = sum; __syncthreads();
        for (int s = 256; s; s >>= 1) { if (tid < s) red[tid] += red[tid + s]; __syncthreads(); }
        invsum[hh] = 1.0f / red[0];
        __syncthreads();
    }

    float a[4][4];
    #pragma unroll
    for (int hh = 0; hh < 4; hh++)
        #pragma unroll
        for (int j = 0; j < 4; j++) a[hh][j] = 0.0f;
    for (int m = warp; m < NTPAT; m += 16) {
        float4 x4 = *(const float4*)(Xb + (size_t)m * CDIM + lane * 4);
        float p0 = slog[0 * NTPAT + m];
        float p1 = slog[1 * NTPAT + m];
        float p2 = slog[2 * NTPAT + m];
        float p3 = slog[3 * NTPAT + m];
        a[0][0] += p0 * x4.x; a[0][1] += p0 * x4.y; a[0][2] += p0 * x4.z; a[0][3] += p0 * x4.w;
        a[1][0] += p1 * x4.x; a[1][1] += p1 * x4.y; a[1][2] += p1 * x4.z; a[1][3] += p1 * x4.w;
        a[2][0] += p2 * x4.x; a[2][1] += p2 * x4.y; a[2][2] += p2 * x4.z; a[2][3] += p2 * x4.w;
        a[3][0] += p3 * x4.x; a[3][1] += p3 * x4.y; a[3][2] += p3 * x4.z; a[3][3] += p3 * x4.w;
    }
    #pragma unroll
    for (int hh = 0; hh < 4; hh++)
        #pragma unroll
        for (int j = 0; j < 4; j++)
            stp[warp * 512 + hh * 128 + lane * 4 + j] = a[hh][j];
    __syncthreads();
    {
        int hh = tid >> 7, c = tid & 127;
        float t = 0.0f;
        #pragma unroll
        for (int w2 = 0; w2 < 16; w2++) t += stp[w2 * 512 + hh * 128 + c];
        st[hh * 128 + c] = t * invsum[hh];
    }
    __syncthreads();

    if (tid < 128) {
        int hh = tid >> 5, d = tid & 31;
        float o = bkv[128 + hh * HD + d];
        const float* wv = Wkv + 128 + hh * HD + d;
        const float* th = st + hh * 128;
        #pragma unroll 4
        for (int c = 0; c < CDIM; c++)
            o += th[c] * wv[(size_t)c * 256];
        out[(size_t)b * CDIM + hh * HD + d] = o;
    }
}

// ---------------- launch ----------------
extern "C" void kernel_launch(void* const* d_in, const int* in_sizes, int n_in,
                              void* d_out, int out_size)
{
    const float* x      = (const float*)d_in[0];
    const float* xtotal = (const float*)d_in[1];
    const float* xavg   = (const float*)d_in[2];
    const float* mask   = (const float*)d_in[3];
    const float* Wq     = (const float*)d_in[4];
    const float* bq     = (const float*)d_in[5];
    const float* Wkv    = (const float*)d_in[6];
    const float* bkv    = (const float*)d_in[7];
    const float* btab   = (const float*)d_in[8];
    const int*   ridx   = (const int*)d_in[9];

    float* out     = (float*)d_out;
    float* out_avg = out + (size_t)200704u * 128u;

    static cudaStream_t s2 = nullptr;
    static cudaEvent_t evF = nullptr, evB = nullptr, evJ = nullptr;
    if (s2 == nullptr) {
        cudaStreamCreateWithFlags(&s2, cudaStreamNonBlocking);
        cudaEventCreateWithFlags(&evF, cudaEventDisableTiming);
        cudaEventCreateWithFlags(&evB, cudaEventDisableTiming);
        cudaEventCreateWithFlags(&evJ, cudaEventDisableTiming);
        cudaFuncSetAttribute(qkv_gemm, cudaFuncAttributeMaxDynamicSharedMemorySize, GEMM_SMEM);
        cudaFuncSetAttribute(win_attn_mma, cudaFuncAttributeMaxDynamicSharedMemorySize, WIN_SMEM);
        cudaFuncSetAttribute(glob_attn3, cudaFuncAttributeMaxDynamicSharedMemorySize, GA_SMEM);
    }

    // fork: bias gather + global path on s2
    cudaEventRecord(evF, 0);
    cudaStreamWaitEvent(s2, evF, 0);
    bias_build_kernel<<<(HEADS * NGT * NTOK + 255) / 256, 256, 0, s2>>>(btab, ridx);
    cudaEventRecord(evB, s2);
    glob_attn3<<<BIMG, 512, GA_SMEM, s2>>>(xtotal, xavg, Wq, bq, Wkv, bkv, out_avg);
    cudaEventRecord(evJ, s2);

    // window path
    qkv_gemm<<<dim3(3, 1600), 256, GEMM_SMEM>>>(x, xavg, Wq, Wkv, bq, bkv);
    cudaStreamWaitEvent(0, evB, 0);
    win_attn_mma<<<NWIN, 512, WIN_SMEM>>>(mask, out);

    // join
    cudaStreamWaitEvent(0, evJ, 0);
}